// round 2
// baseline (speedup 1.0000x reference)
#include <cuda_runtime.h>

#define LRELU_SLOPE 0.2f
#define BN_EPS 1e-5f

#define NIMG 82
#define NQIMG 32
#define CH 64
#define H1 84
#define H2 42
#define H3 21
#define LL 441
#define MM 2205

// ---------------- scratch (device globals; no allocs allowed) ----------------
__device__ float g_A[(size_t)NIMG*CH*H1*H1];   // 148 MB
__device__ float g_Bf[(size_t)NIMG*CH*H2*H2];  // 37 MB
__device__ float g_Cf[(size_t)NIMG*CH*H2*H2];  // 37 MB
__device__ float g_qn[(size_t)NQIMG*LL*CH];
__device__ float g_sn[(size_t)2*5*MM*CH];
__device__ float g_scale[2*CH];
__device__ float g_shift[2*CH];

__device__ __forceinline__ float lrelu(float x){ return x >= 0.f ? x : LRELU_SLOPE*x; }

// ---------------- zero output ----------------
__global__ void zero_kernel(float* out, int n){
    int i = blockIdx.x*256 + threadIdx.x;
    if (i < n) out[i] = 0.f;
}

// ---------------- conv1: 3->64 @ 84x84, pad 1 (writes g_A) ----------------
__global__ void __launch_bounds__(196) conv1_kernel(const float* __restrict__ query,
                                                    const float* __restrict__ support,
                                                    const float* __restrict__ W) {
    __shared__ float sw[64*27];
    __shared__ float sin[3*16*16];
    int n = blockIdx.z;
    int x0 = blockIdx.x*14, y0 = blockIdx.y*14;
    int tx = threadIdx.x, ty = threadIdx.y;
    int tid = ty*14 + tx;
    for (int i = tid; i < 64*27; i += 196) sw[i] = W[i];
    const float* img = (n < NQIMG) ? (query + (size_t)n*3*H1*H1)
                                   : (support + (size_t)(n-NQIMG)*3*H1*H1);
    for (int i = tid; i < 3*256; i += 196) {
        int ci = i >> 8, r = i & 255;
        int gy = y0 - 1 + (r>>4), gx = x0 - 1 + (r&15);
        sin[i] = (gy>=0 && gy<H1 && gx>=0 && gx<H1) ? img[(size_t)ci*H1*H1 + gy*H1 + gx] : 0.f;
    }
    __syncthreads();
    float r[27];
    #pragma unroll
    for (int ci=0;ci<3;ci++)
      #pragma unroll
      for (int dy=0;dy<3;dy++)
        #pragma unroll
        for (int dx=0;dx<3;dx++)
          r[ci*9+dy*3+dx] = sin[ci*256 + (ty+dy)*16 + (tx+dx)];
    int y = y0+ty, x = x0+tx;
    size_t obase = ((size_t)n*CH)*H1*H1 + (size_t)y*H1 + x;
    #pragma unroll 4
    for (int co=0; co<64; co++) {
        float acc = 0.f;
        #pragma unroll
        for (int k=0;k<27;k++) acc += sw[co*27+k]*r[k];
        g_A[obase + (size_t)co*H1*H1] = acc;
    }
}

// ---------------- BN stats per (group, channel): folded scale/shift ----------------
// src selector: 0 = g_A, 1 = g_Bf, 2 = g_Cf
__global__ void bn_stats_kernel(int srcSel, int HW,
                                const float* __restrict__ gamma, const float* __restrict__ beta) {
    const float* src = (srcSel==0) ? g_A : (srcSel==1) ? g_Bf : g_Cf;
    int grp = blockIdx.x >> 6;
    int c = blockIdx.x & 63;
    int n0 = grp ? NQIMG : 0;
    int n1 = grp ? NIMG : NQIMG;
    double s=0.0, s2=0.0;
    for (int n=n0; n<n1; n++) {
        const float* p = src + ((size_t)n*CH + c)*HW;
        for (int i=threadIdx.x; i<HW; i+=blockDim.x) {
            float v = p[i]; s += (double)v; s2 += (double)v*(double)v;
        }
    }
    __shared__ double sh1[256], sh2[256];
    sh1[threadIdx.x]=s; sh2[threadIdx.x]=s2;
    __syncthreads();
    for (int ofs=128; ofs>0; ofs>>=1) {
        if (threadIdx.x<ofs){ sh1[threadIdx.x]+=sh1[threadIdx.x+ofs]; sh2[threadIdx.x]+=sh2[threadIdx.x+ofs]; }
        __syncthreads();
    }
    if (threadIdx.x==0) {
        double cnt = (double)(n1-n0)*HW;
        double mean = sh1[0]/cnt;
        double var  = sh2[0]/cnt - mean*mean;
        float inv = rsqrtf((float)var + BN_EPS);
        float sc = gamma[c]*inv;
        g_scale[grp*64+c] = sc;
        g_shift[grp*64+c] = beta[c] - (float)mean*sc;
    }
}

// ---------------- BN + LReLU + 2x2 maxpool ----------------
// dir 0: g_A -> g_Bf (Hi=84); dir 1: g_Cf -> g_A (Hi=42)
__global__ void bn_pool_kernel(int dir, int Hi) {
    const float* src = dir ? g_Cf : g_A;
    float* dst = dir ? g_A : g_Bf;
    int Ho = Hi >> 1;
    long long total = (long long)NIMG*CH*Ho*Ho;
    long long idx = (long long)blockIdx.x*blockDim.x + threadIdx.x;
    if (idx >= total) return;
    int x = (int)(idx % Ho); long long t = idx / Ho;
    int y = (int)(t % Ho); t /= Ho;
    int c = (int)(t & 63); int n = (int)(t >> 6);
    int grp = (n < NQIMG) ? 0 : 1;
    float sc = g_scale[grp*64+c], sh = g_shift[grp*64+c];
    const float* p = src + (((size_t)n*CH + c)*Hi + 2*y)*Hi + 2*x;
    float a = lrelu(p[0]*sc+sh);
    float b = lrelu(p[1]*sc+sh);
    float c2 = lrelu(p[Hi]*sc+sh);
    float d = lrelu(p[Hi+1]*sc+sh);
    dst[idx] = fmaxf(fmaxf(a,b), fmaxf(c2,d));
}

// ---------------- conv2: 64->64 @ 42x42, pad 1 (g_Bf -> g_Cf) ----------------
__global__ void __launch_bounds__(196) conv2_kernel(const float* __restrict__ W) {
    __shared__ float sin[8*16*16];   // 8 ci x 16x16 halo
    __shared__ float sw[64*8*9];
    int n = blockIdx.z;
    int x0 = blockIdx.x*14, y0 = blockIdx.y*14;
    int tx = threadIdx.x, ty = threadIdx.y;
    int tid = ty*14 + tx;
    float acc[64];
    #pragma unroll
    for (int i=0;i<64;i++) acc[i]=0.f;
    const float* ibase = g_Bf + (size_t)n*CH*H2*H2;
    for (int ck=0; ck<8; ck++) {
        int c0 = ck*8;
        __syncthreads();
        for (int i=tid; i<2048; i+=196) {
            int cic = i>>8, r = i&255;
            int gy = y0-1+(r>>4), gx = x0-1+(r&15);
            sin[i] = (gy>=0 && gy<H2 && gx>=0 && gx<H2)
                   ? ibase[(size_t)(c0+cic)*H2*H2 + gy*H2 + gx] : 0.f;
        }
        for (int i=tid; i<64*72; i+=196) {
            int co = i/72, r = i%72;
            sw[i] = W[(size_t)co*576 + c0*9 + r];
        }
        __syncthreads();
        #pragma unroll
        for (int cic=0;cic<8;cic++) {
            float in9[9];
            #pragma unroll
            for (int dy=0;dy<3;dy++)
              #pragma unroll
              for (int dx=0;dx<3;dx++)
                in9[dy*3+dx] = sin[cic*256 + (ty+dy)*16 + tx+dx];
            #pragma unroll 4
            for (int co=0;co<64;co++) {
                const float* wp = &sw[(co*8+cic)*9];
                float a = acc[co];
                #pragma unroll
                for (int k=0;k<9;k++) a += wp[k]*in9[k];
                acc[co]=a;
            }
        }
    }
    int y = y0+ty, x = x0+tx;
    size_t ob = ((size_t)n*CH)*H2*H2 + (size_t)y*H2 + x;
    #pragma unroll 4
    for (int co=0;co<64;co++) g_Cf[ob + (size_t)co*H2*H2] = acc[co];
}

// ---------------- conv3/conv4: 64->64 @ 21x21 (dir 0: g_A->g_Cf, dir 1: g_Cf->g_Bf) ----
__global__ void __launch_bounds__(448) conv34_kernel(int dir, const float* __restrict__ W) {
    __shared__ float sin[8*529];     // 8 ci x 23x23 halo
    __shared__ float sw[32*8*9];
    const float* src = dir ? g_Cf : g_A;
    float* dst = dir ? g_Bf : g_Cf;
    int n = blockIdx.y;
    int coB = blockIdx.x*32;
    int tid = threadIdx.x;
    float acc[32];
    #pragma unroll
    for (int i=0;i<32;i++) acc[i]=0.f;
    const float* ibase = src + (size_t)n*CH*LL;
    int py = tid/21, px = tid%21;  // valid if tid < 441
    for (int ck=0; ck<8; ck++) {
        int c0 = ck*8;
        __syncthreads();
        for (int i=tid; i<8*529; i+=448) {
            int cic = i/529, r = i%529;
            int gy = r/23 - 1, gx = r%23 - 1;
            sin[i] = (gy>=0 && gy<21 && gx>=0 && gx<21)
                   ? ibase[(size_t)(c0+cic)*LL + gy*21 + gx] : 0.f;
        }
        for (int i=tid; i<32*72; i+=448) {
            int co = i/72, r = i%72;
            sw[i] = W[(size_t)(coB+co)*576 + c0*9 + r];
        }
        __syncthreads();
        if (tid < 441) {
            #pragma unroll
            for (int cic=0;cic<8;cic++) {
                float in9[9];
                #pragma unroll
                for (int dy=0;dy<3;dy++)
                  #pragma unroll
                  for (int dx=0;dx<3;dx++)
                    in9[dy*3+dx] = sin[cic*529 + (py+dy)*23 + px+dx];
                #pragma unroll 4
                for (int co=0;co<32;co++) {
                    const float* wp = &sw[(co*8+cic)*9];
                    float a = acc[co];
                    #pragma unroll
                    for (int k=0;k<9;k++) a += wp[k]*in9[k];
                    acc[co]=a;
                }
            }
        }
    }
    if (tid < 441) {
        size_t ob = ((size_t)n*CH + coB)*LL + tid;
        #pragma unroll 4
        for (int co=0;co<32;co++) dst[ob + (size_t)co*LL] = acc[co];
    }
}

// ---------------- BN + LReLU in place on g_Cf (block 3 output) ----------------
__global__ void bn_apply_kernel() {
    long long total = (long long)NIMG*CH*LL;
    long long idx = (long long)blockIdx.x*256 + threadIdx.x;
    if (idx >= total) return;
    int c = (int)((idx/LL) & 63);
    int n = (int)(idx/((long long)LL*64));
    int grp = (n < NQIMG) ? 0 : 1;
    g_Cf[idx] = lrelu(g_Cf[idx]*g_scale[grp*64+c] + g_shift[grp*64+c]);
}

// ---------------- BN + LReLU + L2-normalize + transpose (src = g_Bf) ----------
__global__ void normalize_kernel() {
    int n = blockIdx.y;
    int l = blockIdx.x*256 + threadIdx.x;
    if (l >= LL) return;
    int grp = (n < NQIMG) ? 0 : 1;
    float v[64];
    float ss = 0.f;
    const float* p = g_Bf + (size_t)n*CH*LL + l;
    #pragma unroll
    for (int c=0;c<64;c++) {
        float t = lrelu(p[(size_t)c*LL]*g_scale[grp*64+c] + g_shift[grp*64+c]);
        v[c] = t; ss += t*t;
    }
    float inv = 1.f / fmaxf(sqrtf(ss), 1e-12f);
    float* dstp;
    if (n < NQIMG) {
        dstp = &g_qn[((size_t)n*LL + l)*64];
    } else {
        int ns = n - NQIMG;
        int b = ns/25, w = (ns%25)/5, s = ns%5;
        dstp = &g_sn[(((size_t)(b*5+w))*MM + (size_t)s*LL + l)*64];
    }
    #pragma unroll
    for (int c=0;c<64;c++) dstp[c] = v[c]*inv;
}

// ---------------- similarity GEMM + top-3 + sum ----------------
// grid (7 l-tiles, 160 (b,q,way)); 256 threads; tile 64L x 64M, micro 4x4.
__global__ void __launch_bounds__(256) sim_kernel(float* __restrict__ out) {
    __shared__ float sQ[64*65];
    __shared__ float sS[64*65];
    __shared__ float smerge[64*16*3];
    __shared__ float bsum;
    int lt = blockIdx.x;
    int bc = blockIdx.y;
    int b = bc/80; int q = (bc/5)%16; int c = bc%5;
    const float* qb = &g_qn[((size_t)(b*16+q))*LL*64];
    const float* sb = &g_sn[((size_t)(b*5+c))*MM*64];
    int tid = threadIdx.x;
    int tr = tid >> 4, tc = tid & 15;
    for (int i=tid; i<4096; i+=256) {
        int rl = i>>6, d = i&63;
        int row = lt*64 + rl;
        sQ[rl*65+d] = (row < LL) ? qb[(size_t)row*64 + d] : 0.f;
    }
    if (tid==0) bsum = 0.f;
    float t0[4], t1[4], t2[4];
    #pragma unroll
    for (int i=0;i<4;i++){ t0[i]=-1e30f; t1[i]=-1e30f; t2[i]=-1e30f; }
    for (int mt=0; mt<35; mt++) {
        __syncthreads();
        for (int i=tid; i<4096; i+=256) {
            int ml = i>>6, d = i&63;
            int m = mt*64 + ml;
            sS[d*65+ml] = (m < MM) ? sb[(size_t)m*64 + d] : 0.f;
        }
        __syncthreads();
        float acc[4][4];
        #pragma unroll
        for (int i=0;i<4;i++)
          #pragma unroll
          for (int j=0;j<4;j++) acc[i][j]=0.f;
        #pragma unroll 8
        for (int d=0; d<64; d++) {
            float qv[4], sv[4];
            #pragma unroll
            for (int i=0;i<4;i++) qv[i] = sQ[(tr+16*i)*65 + d];
            #pragma unroll
            for (int j=0;j<4;j++) sv[j] = sS[d*65 + tc + 16*j];
            #pragma unroll
            for (int i=0;i<4;i++)
              #pragma unroll
              for (int j=0;j<4;j++) acc[i][j] += qv[i]*sv[j];
        }
        #pragma unroll
        for (int j=0;j<4;j++) {
            int m = mt*64 + tc + 16*j;
            if (m < MM) {
                #pragma unroll
                for (int i=0;i<4;i++) {
                    float v = acc[i][j];
                    if (v > t2[i]) {
                        if (v > t1[i]) {
                            t2[i] = t1[i];
                            if (v > t0[i]) { t1[i]=t0[i]; t0[i]=v; } else t1[i]=v;
                        } else t2[i] = v;
                    }
                }
            }
        }
    }
    __syncthreads();
    #pragma unroll
    for (int i=0;i<4;i++) {
        int rl = tr + 16*i;
        smerge[(rl*16+tc)*3+0] = t0[i];
        smerge[(rl*16+tc)*3+1] = t1[i];
        smerge[(rl*16+tc)*3+2] = t2[i];
    }
    __syncthreads();
    if (tid < 64) {
        int row = lt*64 + tid;
        if (row < LL) {
            float a0=-1e30f, a1=-1e30f, a2=-1e30f;
            for (int k=0;k<48;k++) {
                float v = smerge[tid*48 + k];
                if (v > a2) {
                    if (v > a1) { a2=a1; if (v > a0) { a1=a0; a0=v; } else a1=v; }
                    else a2 = v;
                }
            }
            atomicAdd(&bsum, a0+a1+a2);
        }
    }
    __syncthreads();
    if (tid==0) atomicAdd(&out[(b*16+q)*5 + c], bsum);
}

// ---------------- launcher ----------------
extern "C" void kernel_launch(void* const* d_in, const int* in_sizes, int n_in,
                              void* d_out, int out_size) {
    const float* query   = (const float*)d_in[0];
    const float* support = (const float*)d_in[1];
    const float* W1 = (const float*)d_in[2];
    const float* g1 = (const float*)d_in[3];
    const float* b1 = (const float*)d_in[4];
    const float* W2 = (const float*)d_in[5];
    const float* g2 = (const float*)d_in[6];
    const float* b2 = (const float*)d_in[7];
    const float* W3 = (const float*)d_in[8];
    const float* g3 = (const float*)d_in[9];
    const float* b3 = (const float*)d_in[10];
    const float* W4 = (const float*)d_in[11];
    const float* g4 = (const float*)d_in[12];
    const float* b4 = (const float*)d_in[13];
    float* out = (float*)d_out;

    zero_kernel<<<1, 256>>>(out, 160);

    // block 1: conv -> BN stats -> BN+LReLU+pool (84 -> 42): g_A -> g_Bf
    conv1_kernel<<<dim3(6,6,NIMG), dim3(14,14)>>>(query, support, W1);
    bn_stats_kernel<<<128, 256>>>(0, H1*H1, g1, b1);
    {
        long long tot = (long long)NIMG*CH*H2*H2;
        bn_pool_kernel<<<(unsigned)((tot+255)/256), 256>>>(0, H1);
    }
    // block 2: conv -> stats -> pool (42 -> 21): g_Bf -> g_Cf -> g_A
    conv2_kernel<<<dim3(3,3,NIMG), dim3(14,14)>>>(W2);
    bn_stats_kernel<<<128, 256>>>(2, H2*H2, g2, b2);
    {
        long long tot = (long long)NIMG*CH*H3*H3;
        bn_pool_kernel<<<(unsigned)((tot+255)/256), 256>>>(1, H2);
    }
    // block 3: conv -> stats -> apply (21x21): g_A -> g_Cf (in place BN)
    conv34_kernel<<<dim3(2,NIMG), 448>>>(0, W3);
    bn_stats_kernel<<<128, 256>>>(2, LL, g3, b3);
    {
        long long tot = (long long)NIMG*CH*LL;
        bn_apply_kernel<<<(unsigned)((tot+255)/256), 256>>>();
    }
    // block 4: conv -> stats -> BN+LReLU+normalize+transpose: g_Cf -> g_Bf -> qn/sn
    conv34_kernel<<<dim3(2,NIMG), 448>>>(1, W4);
    bn_stats_kernel<<<128, 256>>>(1, LL, g4, b4);
    normalize_kernel<<<dim3(2,NIMG), 256>>>();

    // cosine sim + top-3 + sum
    sim_kernel<<<dim3(7,160), 256>>>(out);
}

// round 6
// speedup vs baseline: 2.2713x; 2.2713x over previous
#include <cuda_runtime.h>
#include <cstdint>

#define LRELU_SLOPE 0.2f
#define BN_EPS 1e-5f

#define NIMG 82
#define NQIMG 32
#define CH 64
#define H1 84
#define H2 42
#define H3 21
#define LL 441
#define MM 2205

// ---------------- scratch (device globals; no allocs allowed) ----------------
__device__ float g_A[(size_t)NIMG*CH*H1*H1];   // 148 MB
__device__ float g_Bf[(size_t)NIMG*CH*H2*H2];  // 37 MB
__device__ float g_Cf[(size_t)NIMG*CH*H2*H2];  // 37 MB
__device__ float g_qn[(size_t)NQIMG*LL*CH];
__device__ float g_sn[(size_t)2*5*MM*CH];
__device__ float g_scale[2*CH];
__device__ float g_shift[2*CH];
__device__ float g_bnsum[2*CH*2];              // [grp][c][{s,s2}]
__device__ float g_WT[64*9*64];                // transposed weights [ci][k][co]

__device__ __forceinline__ float lrelu(float x){ return x >= 0.f ? x : LRELU_SLOPE*x; }

// branchless sorted-triple insert (t0>=t1>=t2)
__device__ __forceinline__ void ins3(float v, float& t0, float& t1, float& t2){
    if (v > t2) {
        float s  = fminf(t0, v);
        t0 = fmaxf(t0, v);
        float s2 = fminf(t1, s);
        t1 = fmaxf(t1, s);
        t2 = fmaxf(t2, s2);
    }
}

// ---------------- zero output + bn accumulators ----------------
__global__ void zero_kernel(float* out){
    int i = threadIdx.x;
    if (i < 160) out[i] = 0.f;
    if (i < 256) g_bnsum[i] = 0.f;
}

// ---------------- weight transpose: W[co][ci][k] -> g_WT[(ci*9+k)*64+co] -----
__global__ void wtrans_kernel(const float* __restrict__ W, int nci){
    int i = blockIdx.x*256 + threadIdx.x;
    int total = nci*9*64;
    if (i >= total) return;
    int co = i & 63;
    int r  = i >> 6;        // ci*9+k
    int ci = r / 9, k = r % 9;
    g_WT[i] = W[(size_t)co*nci*9 + ci*9 + k];
}

// ---------------- conv1: 3->64 @ 84x84, pad 1 (writes g_A) ----------------
__global__ void __launch_bounds__(196,2) conv1_kernel(const float* __restrict__ query,
                                                      const float* __restrict__ support) {
    __shared__ float swt[3*9*64];     // [ci*9+k][co]
    __shared__ float sin[3*16*16];
    int n = blockIdx.z;
    int x0 = blockIdx.x*14, y0 = blockIdx.y*14;
    int tx = threadIdx.x, ty = threadIdx.y;
    int tid = ty*14 + tx;
    for (int i = tid; i < 3*9*64; i += 196) swt[i] = g_WT[i];
    const float* img = (n < NQIMG) ? (query + (size_t)n*3*H1*H1)
                                   : (support + (size_t)(n-NQIMG)*3*H1*H1);
    for (int i = tid; i < 3*256; i += 196) {
        int ci = i >> 8, r = i & 255;
        int gy = y0 - 1 + (r>>4), gx = x0 - 1 + (r&15);
        sin[i] = (gy>=0 && gy<H1 && gx>=0 && gx<H1) ? img[(size_t)ci*H1*H1 + gy*H1 + gx] : 0.f;
    }
    __syncthreads();
    float r[27];
    #pragma unroll
    for (int ci=0;ci<3;ci++)
      #pragma unroll
      for (int dy=0;dy<3;dy++)
        #pragma unroll
        for (int dx=0;dx<3;dx++)
          r[ci*9+dy*3+dx] = sin[ci*256 + (ty+dy)*16 + (tx+dx)];
    float acc[64];
    #pragma unroll
    for (int i=0;i<64;i++) acc[i]=0.f;
    const float4* swt4 = (const float4*)swt;
    #pragma unroll
    for (int kk=0; kk<27; kk++) {
        float v = r[kk];
        #pragma unroll
        for (int c4=0; c4<16; c4++) {
            float4 w = swt4[kk*16 + c4];
            acc[c4*4+0] += w.x*v;
            acc[c4*4+1] += w.y*v;
            acc[c4*4+2] += w.z*v;
            acc[c4*4+3] += w.w*v;
        }
    }
    int y = y0+ty, x = x0+tx;
    size_t obase = ((size_t)n*CH)*H1*H1 + (size_t)y*H1 + x;
    #pragma unroll 4
    for (int co=0; co<64; co++) g_A[obase + (size_t)co*H1*H1] = acc[co];
}

// ---------------- BN partial stats: wide grid, fp32 partials + atomics -------
__global__ void bn_part_kernel(int srcSel, int HW){
    const float* src = (srcSel==0) ? g_A : (srcSel==1) ? g_Bf : g_Cf;
    int gc = blockIdx.x;          // grp*64+c
    int grp = gc >> 6, c = gc & 63;
    int slice = blockIdx.y;
    int n0, n1;
    if (!grp) { n0 = slice*4; n1 = n0+4; }
    else { n0 = 32 + (50*slice)/8; n1 = 32 + (50*(slice+1))/8; }
    float s = 0.f, s2 = 0.f;
    for (int n=n0; n<n1; n++) {
        const float* p = src + ((size_t)n*CH + c)*HW;
        for (int i=threadIdx.x; i<HW; i+=256) {
            float v = p[i]; s += v; s2 += v*v;
        }
    }
    __shared__ float sh1[256], sh2[256];
    sh1[threadIdx.x]=s; sh2[threadIdx.x]=s2;
    __syncthreads();
    for (int ofs=128; ofs>0; ofs>>=1) {
        if (threadIdx.x<ofs){ sh1[threadIdx.x]+=sh1[threadIdx.x+ofs]; sh2[threadIdx.x]+=sh2[threadIdx.x+ofs]; }
        __syncthreads();
    }
    if (threadIdx.x==0) {
        atomicAdd(&g_bnsum[gc*2+0], sh1[0]);
        atomicAdd(&g_bnsum[gc*2+1], sh2[0]);
    }
}

// ---------------- BN finalize: scale/shift, then rezero accumulators ---------
__global__ void bn_fin_kernel(int HW, const float* __restrict__ gamma,
                              const float* __restrict__ beta){
    int t = threadIdx.x;
    if (t >= 128) return;
    int grp = t >> 6, c = t & 63;
    float s  = g_bnsum[t*2+0];
    float s2 = g_bnsum[t*2+1];
    float cnt = (grp ? 50.f : 32.f) * (float)HW;
    float mean = s / cnt;
    float var = s2 / cnt - mean*mean;
    float inv = rsqrtf(var + BN_EPS);
    float sc = gamma[c]*inv;
    g_scale[t] = sc;
    g_shift[t] = beta[c] - mean*sc;
    g_bnsum[t*2+0] = 0.f;
    g_bnsum[t*2+1] = 0.f;
}

// ---------------- BN + LReLU + 2x2 maxpool ----------------
// dir 0: g_A -> g_Bf (Hi=84); dir 1: g_Cf -> g_A (Hi=42)
__global__ void bn_pool_kernel(int dir, int Hi) {
    const float* src = dir ? g_Cf : g_A;
    float* dst = dir ? g_A : g_Bf;
    int Ho = Hi >> 1;
    long long total = (long long)NIMG*CH*Ho*Ho;
    long long idx = (long long)blockIdx.x*blockDim.x + threadIdx.x;
    if (idx >= total) return;
    int x = (int)(idx % Ho); long long t = idx / Ho;
    int y = (int)(t % Ho); t /= Ho;
    int c = (int)(t & 63); int n = (int)(t >> 6);
    int grp = (n < NQIMG) ? 0 : 1;
    float sc = g_scale[grp*64+c], sh = g_shift[grp*64+c];
    const float* p = src + (((size_t)n*CH + c)*Hi + 2*y)*Hi + 2*x;
    float2 r0 = *(const float2*)p;
    float2 r1 = *(const float2*)(p + Hi);
    float a = lrelu(r0.x*sc+sh);
    float b = lrelu(r0.y*sc+sh);
    float c2 = lrelu(r1.x*sc+sh);
    float d = lrelu(r1.y*sc+sh);
    dst[idx] = fmaxf(fmaxf(a,b), fmaxf(c2,d));
}

// ---------------- conv2: 64->64 @ 42x42, pad 1 (g_Bf -> g_Cf) ----------------
__global__ void __launch_bounds__(196,2) conv2_kernel() {
    __shared__ float sin[8*16*16];   // 8 ci x 16x16 halo
    __shared__ float swc[8*9*64];    // [cic*9+k][co]
    int n = blockIdx.z;
    int x0 = blockIdx.x*14, y0 = blockIdx.y*14;
    int tx = threadIdx.x, ty = threadIdx.y;
    int tid = ty*14 + tx;
    float acc[64];
    #pragma unroll
    for (int i=0;i<64;i++) acc[i]=0.f;
    const float* ibase = g_Bf + (size_t)n*CH*H2*H2;
    for (int ck=0; ck<8; ck++) {
        int c0 = ck*8;
        __syncthreads();
        for (int i=tid; i<2048; i+=196) {
            int cic = i>>8, r = i&255;
            int gy = y0-1+(r>>4), gx = x0-1+(r&15);
            sin[i] = (gy>=0 && gy<H2 && gx>=0 && gx<H2)
                   ? ibase[(size_t)(c0+cic)*H2*H2 + gy*H2 + gx] : 0.f;
        }
        {   // contiguous chunk of g_WT: [(c0..c0+8)*9][64]
            const float4* srcw = (const float4*)(g_WT + (size_t)c0*9*64);
            float4* dstw = (float4*)swc;
            for (int i=tid; i<1152; i+=196) dstw[i] = srcw[i];
        }
        __syncthreads();
        const float4* swc4 = (const float4*)swc;
        #pragma unroll
        for (int cic=0;cic<8;cic++) {
            float in9[9];
            #pragma unroll
            for (int dy=0;dy<3;dy++)
              #pragma unroll
              for (int dx=0;dx<3;dx++)
                in9[dy*3+dx] = sin[cic*256 + (ty+dy)*16 + tx+dx];
            #pragma unroll
            for (int k=0;k<9;k++) {
                float v = in9[k];
                #pragma unroll
                for (int c4=0;c4<16;c4++) {
                    float4 w = swc4[(cic*9+k)*16 + c4];
                    acc[c4*4+0] += w.x*v;
                    acc[c4*4+1] += w.y*v;
                    acc[c4*4+2] += w.z*v;
                    acc[c4*4+3] += w.w*v;
                }
            }
        }
    }
    int y = y0+ty, x = x0+tx;
    size_t ob = ((size_t)n*CH)*H2*H2 + (size_t)y*H2 + x;
    #pragma unroll 4
    for (int co=0;co<64;co++) g_Cf[ob + (size_t)co*H2*H2] = acc[co];
}

// ---------------- conv3/conv4 @ 21x21: 4 blocks/img (2 co-halves x 2 row-halves)
// dir 0: g_A (pooled,BN'd) -> g_Cf raw   dir 1: g_Cf (raw; apply BN3+lrelu on read) -> g_Bf raw
// NOTE: BN applies ONLY to in-bounds values; padding stays 0 (post-activation pad).
__global__ void __launch_bounds__(256) conv34_kernel(int dir, int apply) {
    __shared__ float sin[8*13*23];   // 8 ci x up to 13 rows x 23 cols
    __shared__ float swc[8*9*32];    // [cic*9+k][32 co]
    const float* src = dir ? g_Cf : g_A;
    float* dst = dir ? g_Bf : g_Cf;
    int n = blockIdx.y;
    int coH = blockIdx.x & 1;
    int rowH = blockIdx.x >> 1;
    int r0 = rowH ? 11 : 0;
    int nrows = rowH ? 10 : 11;
    int hrows = nrows + 2;
    int grp = (n < NQIMG) ? 0 : 1;
    int tid = threadIdx.x;
    float acc[32];
    #pragma unroll
    for (int i=0;i<32;i++) acc[i]=0.f;
    const float* ibase = src + (size_t)n*CH*LL;
    int ly = tid/21, lx = tid%21;        // valid if tid < nrows*21
    bool act = (tid < nrows*21);
    for (int ck=0; ck<8; ck++) {
        int c0 = ck*8;
        __syncthreads();
        int fillN = 8*hrows*23;
        for (int i=tid; i<fillN; i+=256) {
            int cic = i/(hrows*23);
            int r = i%(hrows*23);
            int yy = r/23, xx = r%23;
            int gy = r0 - 1 + yy, gx = xx - 1;
            float v = 0.f;
            if (gy>=0 && gy<21 && gx>=0 && gx<21) {
                v = ibase[(size_t)(c0+cic)*LL + gy*21 + gx];
                if (apply) v = lrelu(v*g_scale[grp*64+c0+cic] + g_shift[grp*64+c0+cic]);
            }
            sin[i] = v;
        }
        for (int i=tid; i<2304; i+=256) {
            int cic = i/288;
            int rem = i%288;
            int k = rem >> 5, co = rem & 31;
            swc[i] = g_WT[((size_t)(c0+cic)*9+k)*64 + coH*32 + co];
        }
        __syncthreads();
        if (act) {
            const float4* swc4 = (const float4*)swc;
            #pragma unroll
            for (int cic=0;cic<8;cic++) {
                float in9[9];
                #pragma unroll
                for (int dy=0;dy<3;dy++)
                  #pragma unroll
                  for (int dx=0;dx<3;dx++)
                    in9[dy*3+dx] = sin[cic*hrows*23 + (ly+dy)*23 + lx+dx];
                #pragma unroll
                for (int k=0;k<9;k++) {
                    float v = in9[k];
                    #pragma unroll
                    for (int c4=0;c4<8;c4++) {
                        float4 w = swc4[(cic*9+k)*8 + c4];
                        acc[c4*4+0] += w.x*v;
                        acc[c4*4+1] += w.y*v;
                        acc[c4*4+2] += w.z*v;
                        acc[c4*4+3] += w.w*v;
                    }
                }
            }
        }
    }
    if (act) {
        int gy = r0 + ly;
        size_t ob = ((size_t)n*CH + coH*32)*LL + gy*21 + lx;
        #pragma unroll 4
        for (int co=0;co<32;co++) dst[ob + (size_t)co*LL] = acc[co];
    }
}

// ---------------- BN4 + LReLU + L2-normalize + tf32-round + transpose --------
__global__ void normalize_kernel() {
    int n = blockIdx.y;
    int l = blockIdx.x*256 + threadIdx.x;
    if (l >= LL) return;
    int grp = (n < NQIMG) ? 0 : 1;
    float v[64];
    float ss = 0.f;
    const float* p = g_Bf + (size_t)n*CH*LL + l;
    #pragma unroll
    for (int c=0;c<64;c++) {
        float t = lrelu(p[(size_t)c*LL]*g_scale[grp*64+c] + g_shift[grp*64+c]);
        v[c] = t; ss += t*t;
    }
    float inv = 1.f / fmaxf(sqrtf(ss), 1e-12f);
    float* dstp;
    if (n < NQIMG) {
        dstp = &g_qn[((size_t)n*LL + l)*64];
    } else {
        int ns = n - NQIMG;
        int b = ns/25, w = (ns%25)/5, s = ns%5;
        dstp = &g_sn[(((size_t)(b*5+w))*MM + (size_t)s*LL + l)*64];
    }
    #pragma unroll
    for (int c=0;c<64;c++) {
        float o = v[c]*inv;
        uint32_t ot;
        asm("cvt.rna.tf32.f32 %0, %1;" : "=r"(ot) : "f"(o));
        dstp[c] = __uint_as_float(ot);
    }
}

// ---------------- similarity: tf32 mma + top-3 + sum ----------------
// grid (7 l-tiles, 160 (b,q,way)); 256 thr (8 warps). Block tile 64L x 64M.
// warp w: rows 16*(w&3).., cols 32*(w>>2)..  warp tile 16x32 = 4 n-tiles of m16n8.
__global__ void __launch_bounds__(256) sim_kernel(float* __restrict__ out) {
    __shared__ float sQ[64*68];
    __shared__ float sS[64*68];
    __shared__ float smerge[64][2][3];
    __shared__ float bsum;
    int lt = blockIdx.x;
    int bc = blockIdx.y;
    int b = bc/80; int q = (bc/5)%16; int c = bc%5;
    const float* qb = g_qn + ((size_t)(b*16+q))*LL*64;
    const float* sb = g_sn + ((size_t)(b*5+c))*MM*64;
    int tid = threadIdx.x;
    int w = tid >> 5, lane = tid & 31;
    int g = lane >> 2, q4 = lane & 3;
    int rg = w & 3, cg = w >> 2;
    // fill sQ (tf32-rounded fp32)
    {
        int row = tid >> 2; int col = (tid & 3) << 4;
        int grow = lt*64 + row;
        float4* d4 = (float4*)&sQ[row*68 + col];
        if (grow < LL) {
            const float4* s4 = (const float4*)(qb + (size_t)grow*64 + col);
            d4[0]=s4[0]; d4[1]=s4[1]; d4[2]=s4[2]; d4[3]=s4[3];
        } else {
            float4 z = {0,0,0,0};
            d4[0]=z; d4[1]=z; d4[2]=z; d4[3]=z;
        }
    }
    if (tid==0) bsum = 0.f;
    __syncthreads();
    // A fragments, persistent (K=64 -> 8 k-chunks of 8)
    int r0 = rg*16;
    unsigned afr[8][4];
    {
        const float* qa = &sQ[(r0+g)*68 + q4];
        #pragma unroll
        for (int kc=0;kc<8;kc++) {
            afr[kc][0] = __float_as_uint(qa[kc*8]);
            afr[kc][1] = __float_as_uint(qa[8*68 + kc*8]);
            afr[kc][2] = __float_as_uint(qa[kc*8 + 4]);
            afr[kc][3] = __float_as_uint(qa[8*68 + kc*8 + 4]);
        }
    }
    float a0=-1e30f,a1=-1e30f,a2=-1e30f;   // top3 for row r0+g
    float b0_=-1e30f,b1_=-1e30f,b2_=-1e30f; // top3 for row r0+8+g
    int n0 = cg*32;
    for (int mt=0; mt<35; mt++) {
        __syncthreads();
        {   // fill sS: 64 m-rows of this M-tile
            int row = tid >> 2; int col = (tid & 3) << 4;
            int m = mt*64 + row;
            float4* d4 = (float4*)&sS[row*68 + col];
            if (m < MM) {
                const float4* s4 = (const float4*)(sb + (size_t)m*64 + col);
                d4[0]=s4[0]; d4[1]=s4[1]; d4[2]=s4[2]; d4[3]=s4[3];
            } else {
                float4 z = {0,0,0,0};
                d4[0]=z; d4[1]=z; d4[2]=z; d4[3]=z;
            }
        }
        __syncthreads();
        bool tail = (mt == 34);
        #pragma unroll
        for (int nt=0; nt<4; nt++) {
            float c0f=0.f, c1f=0.f, c2f=0.f, c3f=0.f;
            const float* pB = &sS[(n0 + nt*8 + g)*68 + q4];
            #pragma unroll
            for (int kc=0;kc<8;kc++) {
                unsigned bb0 = __float_as_uint(pB[kc*8]);
                unsigned bb1 = __float_as_uint(pB[kc*8 + 4]);
                asm volatile(
                  "mma.sync.aligned.m16n8k8.row.col.f32.tf32.tf32.f32 "
                  "{%0,%1,%2,%3},{%4,%5,%6,%7},{%8,%9},{%0,%1,%2,%3};"
                  : "+f"(c0f), "+f"(c1f), "+f"(c2f), "+f"(c3f)
                  : "r"(afr[kc][0]), "r"(afr[kc][1]), "r"(afr[kc][2]), "r"(afr[kc][3]),
                    "r"(bb0), "r"(bb1));
            }
            if (tail) {
                int col0 = mt*64 + n0 + nt*8 + (q4<<1);
                if (col0   < MM) { ins3(c0f, a0,a1,a2); ins3(c2f, b0_,b1_,b2_); }
                if (col0+1 < MM) { ins3(c1f, a0,a1,a2); ins3(c3f, b0_,b1_,b2_); }
            } else {
                ins3(c0f, a0,a1,a2); ins3(c1f, a0,a1,a2);
                ins3(c2f, b0_,b1_,b2_); ins3(c3f, b0_,b1_,b2_);
            }
        }
    }
    // merge across the 4 lanes (q4) sharing each row
    #pragma unroll
    for (int ofs=1; ofs<=2; ofs<<=1) {
        float o0 = __shfl_xor_sync(0xffffffffu, a0, ofs);
        float o1 = __shfl_xor_sync(0xffffffffu, a1, ofs);
        float o2 = __shfl_xor_sync(0xffffffffu, a2, ofs);
        ins3(o0, a0,a1,a2); ins3(o1, a0,a1,a2); ins3(o2, a0,a1,a2);
        o0 = __shfl_xor_sync(0xffffffffu, b0_, ofs);
        o1 = __shfl_xor_sync(0xffffffffu, b1_, ofs);
        o2 = __shfl_xor_sync(0xffffffffu, b2_, ofs);
        ins3(o0, b0_,b1_,b2_); ins3(o1, b0_,b1_,b2_); ins3(o2, b0_,b1_,b2_);
    }
    if (q4 == 0) {
        int rA = r0 + g;
        smerge[rA][cg][0]=a0; smerge[rA][cg][1]=a1; smerge[rA][cg][2]=a2;
        smerge[rA+8][cg][0]=b0_; smerge[rA+8][cg][1]=b1_; smerge[rA+8][cg][2]=b2_;
    }
    __syncthreads();
    if (tid < 64) {
        float m0 = smerge[tid][0][0], m1 = smerge[tid][0][1], m2 = smerge[tid][0][2];
        ins3(smerge[tid][1][0], m0,m1,m2);
        ins3(smerge[tid][1][1], m0,m1,m2);
        ins3(smerge[tid][1][2], m0,m1,m2);
        int grow = lt*64 + tid;
        if (grow < LL) atomicAdd(&bsum, m0+m1+m2);
    }
    __syncthreads();
    if (tid==0) atomicAdd(&out[(b*16+q)*5 + c], bsum);
}

// ---------------- launcher ----------------
extern "C" void kernel_launch(void* const* d_in, const int* in_sizes, int n_in,
                              void* d_out, int out_size) {
    const float* query   = (const float*)d_in[0];
    const float* support = (const float*)d_in[1];
    const float* W1 = (const float*)d_in[2];
    const float* g1 = (const float*)d_in[3];
    const float* b1 = (const float*)d_in[4];
    const float* W2 = (const float*)d_in[5];
    const float* g2 = (const float*)d_in[6];
    const float* b2 = (const float*)d_in[7];
    const float* W3 = (const float*)d_in[8];
    const float* g3 = (const float*)d_in[9];
    const float* b3 = (const float*)d_in[10];
    const float* W4 = (const float*)d_in[11];
    const float* g4 = (const float*)d_in[12];
    const float* b4 = (const float*)d_in[13];
    float* out = (float*)d_out;

    zero_kernel<<<1, 256>>>(out);

    // block 1: g_A -> (stats) -> pool -> g_Bf
    wtrans_kernel<<<7, 256>>>(W1, 3);
    conv1_kernel<<<dim3(6,6,NIMG), dim3(14,14)>>>(query, support);
    bn_part_kernel<<<dim3(128,8), 256>>>(0, H1*H1);
    bn_fin_kernel<<<1, 128>>>(H1*H1, g1, b1);
    {
        long long tot = (long long)NIMG*CH*H2*H2;
        bn_pool_kernel<<<(unsigned)((tot+255)/256), 256>>>(0, H1);
    }
    // block 2: g_Bf -> g_Cf -> (stats) -> pool -> g_A
    wtrans_kernel<<<144, 256>>>(W2, 64);
    conv2_kernel<<<dim3(3,3,NIMG), dim3(14,14)>>>();
    bn_part_kernel<<<dim3(128,8), 256>>>(2, H2*H2);
    bn_fin_kernel<<<1, 128>>>(H2*H2, g2, b2);
    {
        long long tot = (long long)NIMG*CH*H3*H3;
        bn_pool_kernel<<<(unsigned)((tot+255)/256), 256>>>(1, H2);
    }
    // block 3: g_A -> g_Cf (raw) -> stats3 (BN applied on conv4 read)
    wtrans_kernel<<<144, 256>>>(W3, 64);
    conv34_kernel<<<dim3(4,NIMG), 256>>>(0, 0);
    bn_part_kernel<<<dim3(128,8), 256>>>(2, LL);
    bn_fin_kernel<<<1, 128>>>(LL, g3, b3);
    // block 4: g_Cf (apply BN3) -> g_Bf (raw) -> stats4 -> normalize
    wtrans_kernel<<<144, 256>>>(W4, 64);
    conv34_kernel<<<dim3(4,NIMG), 256>>>(1, 1);
    bn_part_kernel<<<dim3(128,8), 256>>>(1, LL);
    bn_fin_kernel<<<1, 128>>>(LL, g4, b4);
    normalize_kernel<<<dim3(2,NIMG), 256>>>();

    // cosine sim (tf32 tensor cores) + top-3 + sum
    sim_kernel<<<dim3(7,160), 256>>>(out);
}

// round 7
// speedup vs baseline: 3.0260x; 1.3323x over previous
#include <cuda_runtime.h>
#include <cuda_bf16.h>
#include <cstdint>

#define LRELU_SLOPE 0.2f
#define BN_EPS 1e-5f

#define NIMG 82
#define NQIMG 32
#define CH 64
#define H1 84
#define H2 42
#define H3 21
#define LL 441
#define MM 2205

// ---------------- scratch (device globals; no allocs allowed) ----------------
__device__ float g_A[(size_t)NIMG*CH*H1*H1];   // 148 MB
__device__ float g_Bf[(size_t)NIMG*CH*H2*H2];  // 37 MB
__device__ float g_Cf[(size_t)NIMG*CH*H2*H2];  // 37 MB
__device__ float g_qn[(size_t)NQIMG*LL*CH];
__device__ float g_sn[(size_t)2*5*MM*CH];
__device__ float g_scale[2*CH];
__device__ float g_shift[2*CH];
__device__ float g_bnsum[2*CH*2];              // [grp][c][{s,s2}]
__device__ float g_WT[64*9*64];                // transposed weights [ci][k][co]
// conv2 bf16-split weight fragments: [cc(4)][s(9)][nt(8)][lane(32)][reg(2)]
__device__ uint32_t g_W2h[18432];
__device__ uint32_t g_W2l[18432];

__device__ __forceinline__ float lrelu(float x){ return x >= 0.f ? x : LRELU_SLOPE*x; }

// branchless sorted-triple insert (t0>=t1>=t2)
__device__ __forceinline__ void ins3(float v, float& t0, float& t1, float& t2){
    if (v > t2) {
        float s  = fminf(t0, v);
        t0 = fmaxf(t0, v);
        float s2 = fminf(t1, s);
        t1 = fmaxf(t1, s);
        t2 = fmaxf(t2, s2);
    }
}

// split fp32 pair into bf16x2 hi + bf16x2 lo (v = hi + lo, error ~2^-18)
__device__ __forceinline__ void split2(float vx, float vy, uint32_t& hi, uint32_t& lo){
    __nv_bfloat162 h = __floats2bfloat162_rn(vx, vy);
    float hx = __bfloat162float(h.x);
    float hy = __bfloat162float(h.y);
    __nv_bfloat162 l = __floats2bfloat162_rn(vx - hx, vy - hy);
    hi = *reinterpret_cast<uint32_t*>(&h);
    lo = *reinterpret_cast<uint32_t*>(&l);
}

#define MMA_BF16(C, A, b0, b1) \
    asm volatile("mma.sync.aligned.m16n8k16.row.col.f32.bf16.bf16.f32 " \
        "{%0,%1,%2,%3},{%4,%5,%6,%7},{%8,%9},{%0,%1,%2,%3};" \
        : "+f"((C)[0]), "+f"((C)[1]), "+f"((C)[2]), "+f"((C)[3]) \
        : "r"((A)[0]), "r"((A)[1]), "r"((A)[2]), "r"((A)[3]), "r"(b0), "r"(b1))

// ---------------- zero output + bn accumulators ----------------
__global__ void zero_kernel(float* out){
    int i = threadIdx.x;
    if (i < 160) out[i] = 0.f;
    if (i < 256) g_bnsum[i] = 0.f;
}

// ---------------- weight transpose: W[co][ci][k] -> g_WT[(ci*9+k)*64+co] -----
__global__ void wtrans_kernel(const float* __restrict__ W, int nci){
    int i = blockIdx.x*256 + threadIdx.x;
    int total = nci*9*64;
    if (i >= total) return;
    int co = i & 63;
    int r  = i >> 6;        // ci*9+k
    int ci = r / 9, k = r % 9;
    g_WT[i] = W[(size_t)co*nci*9 + ci*9 + k];
}

// ---------------- conv2 weight fragment prep: bf16 split, mma B-layout -------
// B[k][n] for chunk: k = ci within 16-chunk, n = co within 8-tile.
// reg r: k_lo = 2*(t%4) + 8*r, pair (k_lo, k_lo+1); n = t/4.
__global__ void wfrag2_kernel(const float* __restrict__ W2){
    int i = blockIdx.x*256 + threadIdx.x;
    if (i >= 18432) return;
    int r  = i & 1;
    int t  = (i >> 1) & 31;
    int nt = (i >> 6) & 7;
    int rem = i >> 9;          // 0..35
    int s  = rem % 9;
    int cc = rem / 9;
    int q = t & 3, nn = t >> 2;
    int ci = cc*16 + 2*q + 8*r;
    int co = nt*8 + nn;
    float v0 = W2[((size_t)co*64 + ci    )*9 + s];
    float v1 = W2[((size_t)co*64 + ci + 1)*9 + s];
    uint32_t hi, lo;
    split2(v0, v1, hi, lo);
    g_W2h[i] = hi;
    g_W2l[i] = lo;
}

// ---------------- conv1: 3->64 @ 84x84, pad 1 (writes g_A) ----------------
__global__ void __launch_bounds__(196,2) conv1_kernel(const float* __restrict__ query,
                                                      const float* __restrict__ support) {
    __shared__ float swt[3*9*64];     // [ci*9+k][co]
    __shared__ float sin[3*16*16];
    int n = blockIdx.z;
    int x0 = blockIdx.x*14, y0 = blockIdx.y*14;
    int tx = threadIdx.x, ty = threadIdx.y;
    int tid = ty*14 + tx;
    for (int i = tid; i < 3*9*64; i += 196) swt[i] = g_WT[i];
    const float* img = (n < NQIMG) ? (query + (size_t)n*3*H1*H1)
                                   : (support + (size_t)(n-NQIMG)*3*H1*H1);
    for (int i = tid; i < 3*256; i += 196) {
        int ci = i >> 8, r = i & 255;
        int gy = y0 - 1 + (r>>4), gx = x0 - 1 + (r&15);
        sin[i] = (gy>=0 && gy<H1 && gx>=0 && gx<H1) ? img[(size_t)ci*H1*H1 + gy*H1 + gx] : 0.f;
    }
    __syncthreads();
    float r[27];
    #pragma unroll
    for (int ci=0;ci<3;ci++)
      #pragma unroll
      for (int dy=0;dy<3;dy++)
        #pragma unroll
        for (int dx=0;dx<3;dx++)
          r[ci*9+dy*3+dx] = sin[ci*256 + (ty+dy)*16 + (tx+dx)];
    float acc[64];
    #pragma unroll
    for (int i=0;i<64;i++) acc[i]=0.f;
    const float4* swt4 = (const float4*)swt;
    #pragma unroll
    for (int kk=0; kk<27; kk++) {
        float v = r[kk];
        #pragma unroll
        for (int c4=0; c4<16; c4++) {
            float4 w = swt4[kk*16 + c4];
            acc[c4*4+0] += w.x*v;
            acc[c4*4+1] += w.y*v;
            acc[c4*4+2] += w.z*v;
            acc[c4*4+3] += w.w*v;
        }
    }
    int y = y0+ty, x = x0+tx;
    size_t obase = ((size_t)n*CH)*H1*H1 + (size_t)y*H1 + x;
    #pragma unroll 4
    for (int co=0; co<64; co++) g_A[obase + (size_t)co*H1*H1] = acc[co];
}

// ---------------- BN partial stats: wide grid, fp32 partials + atomics -------
__global__ void bn_part_kernel(int srcSel, int HW){
    const float* src = (srcSel==0) ? g_A : (srcSel==1) ? g_Bf : g_Cf;
    int gc = blockIdx.x;          // grp*64+c
    int grp = gc >> 6, c = gc & 63;
    int slice = blockIdx.y;
    int n0, n1;
    if (!grp) { n0 = slice*4; n1 = n0+4; }
    else { n0 = 32 + (50*slice)/8; n1 = 32 + (50*(slice+1))/8; }
    float s = 0.f, s2 = 0.f;
    for (int n=n0; n<n1; n++) {
        const float* p = src + ((size_t)n*CH + c)*HW;
        for (int i=threadIdx.x; i<HW; i+=256) {
            float v = p[i]; s += v; s2 += v*v;
        }
    }
    __shared__ float sh1[256], sh2[256];
    sh1[threadIdx.x]=s; sh2[threadIdx.x]=s2;
    __syncthreads();
    for (int ofs=128; ofs>0; ofs>>=1) {
        if (threadIdx.x<ofs){ sh1[threadIdx.x]+=sh1[threadIdx.x+ofs]; sh2[threadIdx.x]+=sh2[threadIdx.x+ofs]; }
        __syncthreads();
    }
    if (threadIdx.x==0) {
        atomicAdd(&g_bnsum[gc*2+0], sh1[0]);
        atomicAdd(&g_bnsum[gc*2+1], sh2[0]);
    }
}

// ---------------- BN finalize: scale/shift, then rezero accumulators ---------
__global__ void bn_fin_kernel(int HW, const float* __restrict__ gamma,
                              const float* __restrict__ beta){
    int t = threadIdx.x;
    if (t >= 128) return;
    int grp = t >> 6, c = t & 63;
    float s  = g_bnsum[t*2+0];
    float s2 = g_bnsum[t*2+1];
    float cnt = (grp ? 50.f : 32.f) * (float)HW;
    float mean = s / cnt;
    float var = s2 / cnt - mean*mean;
    float inv = rsqrtf(var + BN_EPS);
    float sc = gamma[c]*inv;
    g_scale[t] = sc;
    g_shift[t] = beta[c] - mean*sc;
    g_bnsum[t*2+0] = 0.f;
    g_bnsum[t*2+1] = 0.f;
}

// ---------------- BN + LReLU + 2x2 maxpool ----------------
// dir 0: g_A -> g_Bf (Hi=84); dir 1: g_Cf -> g_A (Hi=42)
__global__ void bn_pool_kernel(int dir, int Hi) {
    const float* src = dir ? g_Cf : g_A;
    float* dst = dir ? g_A : g_Bf;
    int Ho = Hi >> 1;
    long long total = (long long)NIMG*CH*Ho*Ho;
    long long idx = (long long)blockIdx.x*blockDim.x + threadIdx.x;
    if (idx >= total) return;
    int x = (int)(idx % Ho); long long t = idx / Ho;
    int y = (int)(t % Ho); t /= Ho;
    int c = (int)(t & 63); int n = (int)(t >> 6);
    int grp = (n < NQIMG) ? 0 : 1;
    float sc = g_scale[grp*64+c], sh = g_shift[grp*64+c];
    const float* p = src + (((size_t)n*CH + c)*Hi + 2*y)*Hi + 2*x;
    float2 r0 = *(const float2*)p;
    float2 r1 = *(const float2*)(p + Hi);
    float a = lrelu(r0.x*sc+sh);
    float b = lrelu(r0.y*sc+sh);
    float c2 = lrelu(r1.x*sc+sh);
    float d = lrelu(r1.y*sc+sh);
    dst[idx] = fmaxf(fmaxf(a,b), fmaxf(c2,d));
}

// ---------------- conv2 (bf16-split tensor core implicit GEMM) ---------------
// g_Bf (NCHW, 42x42) -> g_Cf (NCHW raw). Per block: image n, 16x16 output tile.
// K loop: 4 chunks of 16 ci; per chunk, 9 shifts of a K=16 GEMM.
// M rows = 16 x-positions of one output row; each warp covers 2 output rows.
// Accuracy: v = hi+lo (bf16 each); hi*hi + hi*lo + lo*hi; error ~2^-18.
__global__ void __launch_bounds__(256,2) conv2_tc() {
    extern __shared__ float sm[];
    float* sIn = sm;                              // [18][18][18pad] floats
    uint32_t* sWh = (uint32_t*)(sm + 5832);       // [9][8][32][2]
    uint32_t* sWl = sWh + 4608;
    int n = blockIdx.y;
    int bx = blockIdx.x;                          // 0..8
    int x0 = (bx % 3) * 16, y0 = (bx / 3) * 16;
    int tid = threadIdx.x;
    int w = tid >> 5, lane = tid & 31, g = lane >> 2, q4 = lane & 3;
    float acc[2][8][4];
    #pragma unroll
    for (int i=0;i<2;i++)
      #pragma unroll
      for (int nt=0;nt<8;nt++)
        #pragma unroll
        for (int r=0;r<4;r++) acc[i][nt][r]=0.f;
    const float* ibase = g_Bf + (size_t)n*CH*H2*H2;
    for (int cc=0; cc<4; cc++) {
        __syncthreads();
        // stage input halo tile, channel-last [yy][xx][ci], xx-fastest gmem reads
        for (int i=tid; i<5184; i+=256) {
            int ci = i / 324, rem = i % 324, yy = rem / 18, xx = rem % 18;
            int gy = y0 - 1 + yy, gx = x0 - 1 + xx;
            float v = 0.f;
            if (gy>=0 && gy<H2 && gx>=0 && gx<H2)
                v = ibase[(size_t)(cc*16+ci)*H2*H2 + gy*H2 + gx];
            sIn[(yy*18 + xx)*18 + ci] = v;
        }
        // stage weight fragments for this ci-chunk
        {
            const uint4* sh = (const uint4*)(g_W2h + cc*4608);
            const uint4* sl = (const uint4*)(g_W2l + cc*4608);
            uint4* dh = (uint4*)sWh;
            uint4* dl = (uint4*)sWl;
            for (int i=tid; i<1152; i+=256) { dh[i]=sh[i]; dl[i]=sl[i]; }
        }
        __syncthreads();
        for (int s=0; s<9; s++) {
            int dy = s / 3, dx = s - 3*dy;
            uint32_t Ah[2][4], Al[2][4];
            #pragma unroll
            for (int i=0;i<2;i++) {
                int yy = 2*w + i + dy;
                const float* pl = &sIn[(yy*18 + (g + dx))*18];
                const float* ph = &sIn[(yy*18 + (g + 8 + dx))*18];
                float2 v0 = *(const float2*)(pl + 2*q4);       // row g,  k 2q..2q+1
                float2 v1 = *(const float2*)(ph + 2*q4);       // row g+8
                float2 v2 = *(const float2*)(pl + 2*q4 + 8);   // row g,  k+8
                float2 v3 = *(const float2*)(ph + 2*q4 + 8);   // row g+8, k+8
                split2(v0.x, v0.y, Ah[i][0], Al[i][0]);
                split2(v1.x, v1.y, Ah[i][1], Al[i][1]);
                split2(v2.x, v2.y, Ah[i][2], Al[i][2]);
                split2(v3.x, v3.y, Ah[i][3], Al[i][3]);
            }
            #pragma unroll
            for (int nt=0; nt<8; nt++) {
                int wb = s*512 + nt*64 + lane*2;
                uint32_t bh0 = sWh[wb], bh1 = sWh[wb+1];
                uint32_t bl0 = sWl[wb], bl1 = sWl[wb+1];
                #pragma unroll
                for (int i=0;i<2;i++) {
                    MMA_BF16(acc[i][nt], Ah[i], bh0, bh1);
                    MMA_BF16(acc[i][nt], Ah[i], bl0, bl1);
                    MMA_BF16(acc[i][nt], Al[i], bh0, bh1);
                }
            }
        }
    }
    // store: C row r -> x = x0+r; c0/c1: x0+g, co/co+1; c2/c3: x0+g+8
    #pragma unroll
    for (int i=0;i<2;i++) {
        int y = y0 + 2*w + i;
        if (y >= H2) continue;
        int xA = x0 + g, xB = x0 + g + 8;
        bool vB = (xB < H2);
        #pragma unroll
        for (int nt=0; nt<8; nt++) {
            int co = nt*8 + 2*q4;
            size_t p0 = ((size_t)(n*CH + co    )*H2 + y)*H2;
            size_t p1 = ((size_t)(n*CH + co + 1)*H2 + y)*H2;
            g_Cf[p0 + xA] = acc[i][nt][0];
            g_Cf[p1 + xA] = acc[i][nt][1];
            if (vB) {
                g_Cf[p0 + xB] = acc[i][nt][2];
                g_Cf[p1 + xB] = acc[i][nt][3];
            }
        }
    }
}

// ---------------- conv3/conv4 @ 21x21: 4 blocks/img (2 co-halves x 2 row-halves)
// dir 0: g_A (pooled,BN'd) -> g_Cf raw   dir 1: g_Cf (raw; apply BN3+lrelu on read) -> g_Bf raw
// NOTE: BN applies ONLY to in-bounds values; padding stays 0 (post-activation pad).
__global__ void __launch_bounds__(256) conv34_kernel(int dir, int apply) {
    __shared__ float sin[8*13*23];   // 8 ci x up to 13 rows x 23 cols
    __shared__ float swc[8*9*32];    // [cic*9+k][32 co]
    const float* src = dir ? g_Cf : g_A;
    float* dst = dir ? g_Bf : g_Cf;
    int n = blockIdx.y;
    int coH = blockIdx.x & 1;
    int rowH = blockIdx.x >> 1;
    int r0 = rowH ? 11 : 0;
    int nrows = rowH ? 10 : 11;
    int hrows = nrows + 2;
    int grp = (n < NQIMG) ? 0 : 1;
    int tid = threadIdx.x;
    float acc[32];
    #pragma unroll
    for (int i=0;i<32;i++) acc[i]=0.f;
    const float* ibase = src + (size_t)n*CH*LL;
    int ly = tid/21, lx = tid%21;        // valid if tid < nrows*21
    bool act = (tid < nrows*21);
    for (int ck=0; ck<8; ck++) {
        int c0 = ck*8;
        __syncthreads();
        int fillN = 8*hrows*23;
        for (int i=tid; i<fillN; i+=256) {
            int cic = i/(hrows*23);
            int r = i%(hrows*23);
            int yy = r/23, xx = r%23;
            int gy = r0 - 1 + yy, gx = xx - 1;
            float v = 0.f;
            if (gy>=0 && gy<21 && gx>=0 && gx<21) {
                v = ibase[(size_t)(c0+cic)*LL + gy*21 + gx];
                if (apply) v = lrelu(v*g_scale[grp*64+c0+cic] + g_shift[grp*64+c0+cic]);
            }
            sin[i] = v;
        }
        for (int i=tid; i<2304; i+=256) {
            int cic = i/288;
            int rem = i%288;
            int k = rem >> 5, co = rem & 31;
            swc[i] = g_WT[((size_t)(c0+cic)*9+k)*64 + coH*32 + co];
        }
        __syncthreads();
        if (act) {
            const float4* swc4 = (const float4*)swc;
            #pragma unroll
            for (int cic=0;cic<8;cic++) {
                float in9[9];
                #pragma unroll
                for (int dy=0;dy<3;dy++)
                  #pragma unroll
                  for (int dx=0;dx<3;dx++)
                    in9[dy*3+dx] = sin[cic*hrows*23 + (ly+dy)*23 + lx+dx];
                #pragma unroll
                for (int k=0;k<9;k++) {
                    float v = in9[k];
                    #pragma unroll
                    for (int c4=0;c4<8;c4++) {
                        float4 w = swc4[(cic*9+k)*8 + c4];
                        acc[c4*4+0] += w.x*v;
                        acc[c4*4+1] += w.y*v;
                        acc[c4*4+2] += w.z*v;
                        acc[c4*4+3] += w.w*v;
                    }
                }
            }
        }
    }
    if (act) {
        int gy = r0 + ly;
        size_t ob = ((size_t)n*CH + coH*32)*LL + gy*21 + lx;
        #pragma unroll 4
        for (int co=0;co<32;co++) dst[ob + (size_t)co*LL] = acc[co];
    }
}

// ---------------- BN4 + LReLU + L2-normalize + tf32-round + transpose --------
__global__ void normalize_kernel() {
    int n = blockIdx.y;
    int l = blockIdx.x*256 + threadIdx.x;
    if (l >= LL) return;
    int grp = (n < NQIMG) ? 0 : 1;
    float v[64];
    float ss = 0.f;
    const float* p = g_Bf + (size_t)n*CH*LL + l;
    #pragma unroll
    for (int c=0;c<64;c++) {
        float t = lrelu(p[(size_t)c*LL]*g_scale[grp*64+c] + g_shift[grp*64+c]);
        v[c] = t; ss += t*t;
    }
    float inv = 1.f / fmaxf(sqrtf(ss), 1e-12f);
    float* dstp;
    if (n < NQIMG) {
        dstp = &g_qn[((size_t)n*LL + l)*64];
    } else {
        int ns = n - NQIMG;
        int b = ns/25, w = (ns%25)/5, s = ns%5;
        dstp = &g_sn[(((size_t)(b*5+w))*MM + (size_t)s*LL + l)*64];
    }
    #pragma unroll
    for (int c=0;c<64;c++) {
        float o = v[c]*inv;
        uint32_t ot;
        asm("cvt.rna.tf32.f32 %0, %1;" : "=r"(ot) : "f"(o));
        dstp[c] = __uint_as_float(ot);
    }
}

// ---------------- similarity: tf32 mma + top-3 + sum ----------------
__global__ void __launch_bounds__(256) sim_kernel(float* __restrict__ out) {
    __shared__ float sQ[64*68];
    __shared__ float sS[64*68];
    __shared__ float smerge[64][2][3];
    __shared__ float bsum;
    int lt = blockIdx.x;
    int bc = blockIdx.y;
    int b = bc/80; int q = (bc/5)%16; int c = bc%5;
    const float* qb = g_qn + ((size_t)(b*16+q))*LL*64;
    const float* sb = g_sn + ((size_t)(b*5+c))*MM*64;
    int tid = threadIdx.x;
    int w = tid >> 5, lane = tid & 31;
    int g = lane >> 2, q4 = lane & 3;
    int rg = w & 3, cg = w >> 2;
    {
        int row = tid >> 2; int col = (tid & 3) << 4;
        int grow = lt*64 + row;
        float4* d4 = (float4*)&sQ[row*68 + col];
        if (grow < LL) {
            const float4* s4 = (const float4*)(qb + (size_t)grow*64 + col);
            d4[0]=s4[0]; d4[1]=s4[1]; d4[2]=s4[2]; d4[3]=s4[3];
        } else {
            float4 z = {0,0,0,0};
            d4[0]=z; d4[1]=z; d4[2]=z; d4[3]=z;
        }
    }
    if (tid==0) bsum = 0.f;
    __syncthreads();
    int r0 = rg*16;
    unsigned afr[8][4];
    {
        const float* qa = &sQ[(r0+g)*68 + q4];
        #pragma unroll
        for (int kc=0;kc<8;kc++) {
            afr[kc][0] = __float_as_uint(qa[kc*8]);
            afr[kc][1] = __float_as_uint(qa[8*68 + kc*8]);
            afr[kc][2] = __float_as_uint(qa[kc*8 + 4]);
            afr[kc][3] = __float_as_uint(qa[8*68 + kc*8 + 4]);
        }
    }
    float a0=-1e30f,a1=-1e30f,a2=-1e30f;
    float b0_=-1e30f,b1_=-1e30f,b2_=-1e30f;
    int n0 = cg*32;
    for (int mt=0; mt<35; mt++) {
        __syncthreads();
        {
            int row = tid >> 2; int col = (tid & 3) << 4;
            int m = mt*64 + row;
            float4* d4 = (float4*)&sS[row*68 + col];
            if (m < MM) {
                const float4* s4 = (const float4*)(sb + (size_t)m*64 + col);
                d4[0]=s4[0]; d4[1]=s4[1]; d4[2]=s4[2]; d4[3]=s4[3];
            } else {
                float4 z = {0,0,0,0};
                d4[0]=z; d4[1]=z; d4[2]=z; d4[3]=z;
            }
        }
        __syncthreads();
        bool tail = (mt == 34);
        #pragma unroll
        for (int nt=0; nt<4; nt++) {
            float c0f=0.f, c1f=0.f, c2f=0.f, c3f=0.f;
            const float* pB = &sS[(n0 + nt*8 + g)*68 + q4];
            #pragma unroll
            for (int kc=0;kc<8;kc++) {
                unsigned bb0 = __float_as_uint(pB[kc*8]);
                unsigned bb1 = __float_as_uint(pB[kc*8 + 4]);
                asm volatile(
                  "mma.sync.aligned.m16n8k8.row.col.f32.tf32.tf32.f32 "
                  "{%0,%1,%2,%3},{%4,%5,%6,%7},{%8,%9},{%0,%1,%2,%3};"
                  : "+f"(c0f), "+f"(c1f), "+f"(c2f), "+f"(c3f)
                  : "r"(afr[kc][0]), "r"(afr[kc][1]), "r"(afr[kc][2]), "r"(afr[kc][3]),
                    "r"(bb0), "r"(bb1));
            }
            if (tail) {
                int col0 = mt*64 + n0 + nt*8 + (q4<<1);
                if (col0   < MM) { ins3(c0f, a0,a1,a2); ins3(c2f, b0_,b1_,b2_); }
                if (col0+1 < MM) { ins3(c1f, a0,a1,a2); ins3(c3f, b0_,b1_,b2_); }
            } else {
                ins3(c0f, a0,a1,a2); ins3(c1f, a0,a1,a2);
                ins3(c2f, b0_,b1_,b2_); ins3(c3f, b0_,b1_,b2_);
            }
        }
    }
    #pragma unroll
    for (int ofs=1; ofs<=2; ofs<<=1) {
        float o0 = __shfl_xor_sync(0xffffffffu, a0, ofs);
        float o1 = __shfl_xor_sync(0xffffffffu, a1, ofs);
        float o2 = __shfl_xor_sync(0xffffffffu, a2, ofs);
        ins3(o0, a0,a1,a2); ins3(o1, a0,a1,a2); ins3(o2, a0,a1,a2);
        o0 = __shfl_xor_sync(0xffffffffu, b0_, ofs);
        o1 = __shfl_xor_sync(0xffffffffu, b1_, ofs);
        o2 = __shfl_xor_sync(0xffffffffu, b2_, ofs);
        ins3(o0, b0_,b1_,b2_); ins3(o1, b0_,b1_,b2_); ins3(o2, b0_,b1_,b2_);
    }
    if (q4 == 0) {
        int rA = r0 + g;
        smerge[rA][cg][0]=a0; smerge[rA][cg][1]=a1; smerge[rA][cg][2]=a2;
        smerge[rA+8][cg][0]=b0_; smerge[rA+8][cg][1]=b1_; smerge[rA+8][cg][2]=b2_;
    }
    __syncthreads();
    if (tid < 64) {
        float m0 = smerge[tid][0][0], m1 = smerge[tid][0][1], m2 = smerge[tid][0][2];
        ins3(smerge[tid][1][0], m0,m1,m2);
        ins3(smerge[tid][1][1], m0,m1,m2);
        ins3(smerge[tid][1][2], m0,m1,m2);
        int grow = lt*64 + tid;
        if (grow < LL) atomicAdd(&bsum, m0+m1+m2);
    }
    __syncthreads();
    if (tid==0) atomicAdd(&out[(b*16+q)*5 + c], bsum);
}

// ---------------- launcher ----------------
extern "C" void kernel_launch(void* const* d_in, const int* in_sizes, int n_in,
                              void* d_out, int out_size) {
    const float* query   = (const float*)d_in[0];
    const float* support = (const float*)d_in[1];
    const float* W1 = (const float*)d_in[2];
    const float* g1 = (const float*)d_in[3];
    const float* b1 = (const float*)d_in[4];
    const float* W2 = (const float*)d_in[5];
    const float* g2 = (const float*)d_in[6];
    const float* b2 = (const float*)d_in[7];
    const float* W3 = (const float*)d_in[8];
    const float* g3 = (const float*)d_in[9];
    const float* b3 = (const float*)d_in[10];
    const float* W4 = (const float*)d_in[11];
    const float* g4 = (const float*)d_in[12];
    const float* b4 = (const float*)d_in[13];
    float* out = (float*)d_out;

    const int CONV2_SMEM = 5832*4 + 18432*4;   // 23328 + 73728/... = sIn + sWh + sWl
    // sIn 5832 floats + (4608+4608) u32 = 60192 bytes
    (void)CONV2_SMEM;
    cudaFuncSetAttribute(conv2_tc, cudaFuncAttributeMaxDynamicSharedMemorySize, 60192);

    zero_kernel<<<1, 256>>>(out);

    // block 1: g_A -> (stats) -> pool -> g_Bf
    wtrans_kernel<<<7, 256>>>(W1, 3);
    wfrag2_kernel<<<72, 256>>>(W2);
    conv1_kernel<<<dim3(6,6,NIMG), dim3(14,14)>>>(query, support);
    bn_part_kernel<<<dim3(128,8), 256>>>(0, H1*H1);
    bn_fin_kernel<<<1, 128>>>(H1*H1, g1, b1);
    {
        long long tot = (long long)NIMG*CH*H2*H2;
        bn_pool_kernel<<<(unsigned)((tot+255)/256), 256>>>(0, H1);
    }
    // block 2: g_Bf -> g_Cf (tensor cores) -> (stats) -> pool -> g_A
    conv2_tc<<<dim3(9,NIMG), 256, 60192>>>();
    bn_part_kernel<<<dim3(128,8), 256>>>(2, H2*H2);
    bn_fin_kernel<<<1, 128>>>(H2*H2, g2, b2);
    {
        long long tot = (long long)NIMG*CH*H3*H3;
        bn_pool_kernel<<<(unsigned)((tot+255)/256), 256>>>(1, H2);
    }
    // block 3: g_A -> g_Cf (raw) -> stats3 (BN applied on conv4 read)
    wtrans_kernel<<<144, 256>>>(W3, 64);
    conv34_kernel<<<dim3(4,NIMG), 256>>>(0, 0);
    bn_part_kernel<<<dim3(128,8), 256>>>(2, LL);
    bn_fin_kernel<<<1, 128>>>(LL, g3, b3);
    // block 4: g_Cf (apply BN3) -> g_Bf (raw) -> stats4 -> normalize
    wtrans_kernel<<<144, 256>>>(W4, 64);
    conv34_kernel<<<dim3(4,NIMG), 256>>>(1, 1);
    bn_part_kernel<<<dim3(128,8), 256>>>(1, LL);
    bn_fin_kernel<<<1, 128>>>(LL, g4, b4);
    normalize_kernel<<<dim3(2,NIMG), 256>>>();

    // cosine sim (tf32 tensor cores) + top-3 + sum
    sim_kernel<<<dim3(7,160), 256>>>(out);
}

// round 8
// speedup vs baseline: 3.5538x; 1.1744x over previous
#include <cuda_runtime.h>
#include <cuda_bf16.h>
#include <cstdint>

#define LRELU_SLOPE 0.2f
#define BN_EPS 1e-5f

#define NIMG 82
#define NQIMG 32
#define CH 64
#define H1 84
#define H2 42
#define H3 21
#define LL 441
#define MM 2205

// ---------------- scratch (device globals; no allocs allowed) ----------------
__device__ float g_A[(size_t)NIMG*CH*H1*H1];   // 148 MB
__device__ float g_Bf[(size_t)NIMG*CH*H2*H2];  // 37 MB
__device__ float g_Cf[(size_t)NIMG*CH*H2*H2];  // 37 MB
__device__ float g_qn[(size_t)NQIMG*LL*CH];
__device__ float g_sn[(size_t)2*5*MM*CH];
__device__ float g_scale[2*CH];
__device__ float g_shift[2*CH];
__device__ float g_bnsum[2*CH*2];              // [grp][c][{s,s2}]
__device__ float g_WT[64*9*64];                // transposed weights [ci][k][co] (conv1)
// bf16-split weight fragments: [cc(4)][s(9)][nt(8)][lane(32)][reg(2)]
__device__ uint32_t g_W2h[18432];
__device__ uint32_t g_W2l[18432];
__device__ uint32_t g_W3h[18432];
__device__ uint32_t g_W3l[18432];
__device__ uint32_t g_W4h[18432];
__device__ uint32_t g_W4l[18432];

__device__ __forceinline__ float lrelu(float x){ return x >= 0.f ? x : LRELU_SLOPE*x; }

// branchless sorted-triple insert (t0>=t1>=t2)
__device__ __forceinline__ void ins3(float v, float& t0, float& t1, float& t2){
    if (v > t2) {
        float s  = fminf(t0, v);
        t0 = fmaxf(t0, v);
        float s2 = fminf(t1, s);
        t1 = fmaxf(t1, s);
        t2 = fmaxf(t2, s2);
    }
}

// split fp32 pair into bf16x2 hi + bf16x2 lo (v = hi + lo, error ~2^-18)
__device__ __forceinline__ void split2(float vx, float vy, uint32_t& hi, uint32_t& lo){
    __nv_bfloat162 h = __floats2bfloat162_rn(vx, vy);
    float hx = __bfloat162float(h.x);
    float hy = __bfloat162float(h.y);
    __nv_bfloat162 l = __floats2bfloat162_rn(vx - hx, vy - hy);
    hi = *reinterpret_cast<uint32_t*>(&h);
    lo = *reinterpret_cast<uint32_t*>(&l);
}

#define MMA_BF16(C, A, b0, b1) \
    asm volatile("mma.sync.aligned.m16n8k16.row.col.f32.bf16.bf16.f32 " \
        "{%0,%1,%2,%3},{%4,%5,%6,%7},{%8,%9},{%0,%1,%2,%3};" \
        : "+f"((C)[0]), "+f"((C)[1]), "+f"((C)[2]), "+f"((C)[3]) \
        : "r"((A)[0]), "r"((A)[1]), "r"((A)[2]), "r"((A)[3]), "r"(b0), "r"(b1))

// ---------------- zero output + bn accumulators ----------------
__global__ void zero_kernel(float* out){
    int i = threadIdx.x;
    if (i < 160) out[i] = 0.f;
    if (i < 256) g_bnsum[i] = 0.f;
}

// ---------------- weight transpose: W[co][ci][k] -> g_WT[(ci*9+k)*64+co] -----
__global__ void wtrans_kernel(const float* __restrict__ W, int nci){
    int i = blockIdx.x*256 + threadIdx.x;
    int total = nci*9*64;
    if (i >= total) return;
    int co = i & 63;
    int r  = i >> 6;        // ci*9+k
    int ci = r / 9, k = r % 9;
    g_WT[i] = W[(size_t)co*nci*9 + ci*9 + k];
}

// ---------------- weight fragment prep (64ci x 64co conv): bf16 split --------
// which: 2 -> g_W2, 3 -> g_W3, 4 -> g_W4
__global__ void wfrag_kernel(const float* __restrict__ W, int which){
    int i = blockIdx.x*256 + threadIdx.x;
    if (i >= 18432) return;
    int r  = i & 1;
    int t  = (i >> 1) & 31;
    int nt = (i >> 6) & 7;
    int rem = i >> 9;          // 0..35
    int s  = rem % 9;
    int cc = rem / 9;
    int q = t & 3, nn = t >> 2;
    int ci = cc*16 + 2*q + 8*r;
    int co = nt*8 + nn;
    float v0 = W[((size_t)co*64 + ci    )*9 + s];
    float v1 = W[((size_t)co*64 + ci + 1)*9 + s];
    uint32_t hi, lo;
    split2(v0, v1, hi, lo);
    if (which == 2)      { g_W2h[i] = hi; g_W2l[i] = lo; }
    else if (which == 3) { g_W3h[i] = hi; g_W3l[i] = lo; }
    else                 { g_W4h[i] = hi; g_W4l[i] = lo; }
}

// ---------------- conv1: 3->64 @ 84x84, pad 1 (writes g_A) ----------------
// block: 16x16 spatial tile x 32-co half; 256 threads; grid (36, 2, NIMG)
__global__ void __launch_bounds__(256,3) conv1_kernel(const float* __restrict__ query,
                                                      const float* __restrict__ support) {
    __shared__ float swt[27*32];      // [ci*9+k][co-half]
    __shared__ float sin[3*18*18];    // halo tile per ci
    int n = blockIdx.z, coH = blockIdx.y;
    int bx = blockIdx.x;
    int x0 = (bx % 6) * 16, y0 = (bx / 6) * 16;
    int tid = threadIdx.x;
    int tx = tid & 15, ty = tid >> 4;
    for (int i = tid; i < 864; i += 256) {
        int kk = i >> 5, co = i & 31;
        swt[i] = g_WT[kk*64 + coH*32 + co];
    }
    const float* img = (n < NQIMG) ? (query + (size_t)n*3*H1*H1)
                                   : (support + (size_t)(n-NQIMG)*3*H1*H1);
    for (int i = tid; i < 972; i += 256) {
        int ci = i / 324, rem = i % 324;
        int yy = rem / 18, xx = rem % 18;
        int gy = y0 - 1 + yy, gx = x0 - 1 + xx;
        sin[i] = (gy>=0 && gy<H1 && gx>=0 && gx<H1) ? img[(size_t)ci*H1*H1 + gy*H1 + gx] : 0.f;
    }
    __syncthreads();
    float r[27];
    #pragma unroll
    for (int ci=0;ci<3;ci++)
      #pragma unroll
      for (int dy=0;dy<3;dy++)
        #pragma unroll
        for (int dx=0;dx<3;dx++)
          r[ci*9+dy*3+dx] = sin[ci*324 + (ty+dy)*18 + (tx+dx)];
    float acc[32];
    #pragma unroll
    for (int i=0;i<32;i++) acc[i]=0.f;
    const float4* swt4 = (const float4*)swt;
    #pragma unroll
    for (int kk=0; kk<27; kk++) {
        float v = r[kk];
        #pragma unroll
        for (int c4=0; c4<8; c4++) {
            float4 w = swt4[kk*8 + c4];
            acc[c4*4+0] += w.x*v;
            acc[c4*4+1] += w.y*v;
            acc[c4*4+2] += w.z*v;
            acc[c4*4+3] += w.w*v;
        }
    }
    int y = y0+ty, x = x0+tx;
    if (y < H1 && x < H1) {
        size_t obase = ((size_t)n*CH + coH*32)*H1*H1 + (size_t)y*H1 + x;
        #pragma unroll 4
        for (int co=0; co<32; co++) g_A[obase + (size_t)co*H1*H1] = acc[co];
    }
}

// ---------------- BN partial stats: wide grid, fp32 partials + atomics -------
__global__ void bn_part_kernel(int srcSel, int HW){
    const float* src = (srcSel==0) ? g_A : (srcSel==1) ? g_Bf : g_Cf;
    int gc = blockIdx.x;          // grp*64+c
    int grp = gc >> 6, c = gc & 63;
    int slice = blockIdx.y;
    int n0, n1;
    if (!grp) { n0 = slice*4; n1 = n0+4; }
    else { n0 = 32 + (50*slice)/8; n1 = 32 + (50*(slice+1))/8; }
    float s = 0.f, s2 = 0.f;
    for (int n=n0; n<n1; n++) {
        const float* p = src + ((size_t)n*CH + c)*HW;
        for (int i=threadIdx.x; i<HW; i+=256) {
            float v = p[i]; s += v; s2 += v*v;
        }
    }
    __shared__ float sh1[256], sh2[256];
    sh1[threadIdx.x]=s; sh2[threadIdx.x]=s2;
    __syncthreads();
    for (int ofs=128; ofs>0; ofs>>=1) {
        if (threadIdx.x<ofs){ sh1[threadIdx.x]+=sh1[threadIdx.x+ofs]; sh2[threadIdx.x]+=sh2[threadIdx.x+ofs]; }
        __syncthreads();
    }
    if (threadIdx.x==0) {
        atomicAdd(&g_bnsum[gc*2+0], sh1[0]);
        atomicAdd(&g_bnsum[gc*2+1], sh2[0]);
    }
}

// ---------------- BN finalize: scale/shift, then rezero accumulators ---------
__global__ void bn_fin_kernel(int HW, const float* __restrict__ gamma,
                              const float* __restrict__ beta){
    int t = threadIdx.x;
    if (t >= 128) return;
    int grp = t >> 6, c = t & 63;
    float s  = g_bnsum[t*2+0];
    float s2 = g_bnsum[t*2+1];
    float cnt = (grp ? 50.f : 32.f) * (float)HW;
    float mean = s / cnt;
    float var = s2 / cnt - mean*mean;
    float inv = rsqrtf(var + BN_EPS);
    float sc = gamma[c]*inv;
    g_scale[t] = sc;
    g_shift[t] = beta[c] - mean*sc;
    g_bnsum[t*2+0] = 0.f;
    g_bnsum[t*2+1] = 0.f;
}

// ---------------- BN + LReLU + 2x2 maxpool ----------------
// dir 0: g_A -> g_Bf (Hi=84); dir 1: g_Cf -> g_A (Hi=42)
__global__ void bn_pool_kernel(int dir, int Hi) {
    const float* src = dir ? g_Cf : g_A;
    float* dst = dir ? g_A : g_Bf;
    int Ho = Hi >> 1;
    long long total = (long long)NIMG*CH*Ho*Ho;
    long long idx = (long long)blockIdx.x*blockDim.x + threadIdx.x;
    if (idx >= total) return;
    int x = (int)(idx % Ho); long long t = idx / Ho;
    int y = (int)(t % Ho); t /= Ho;
    int c = (int)(t & 63); int n = (int)(t >> 6);
    int grp = (n < NQIMG) ? 0 : 1;
    float sc = g_scale[grp*64+c], sh = g_shift[grp*64+c];
    const float* p = src + (((size_t)n*CH + c)*Hi + 2*y)*Hi + 2*x;
    float2 r0 = *(const float2*)p;
    float2 r1 = *(const float2*)(p + Hi);
    float a = lrelu(r0.x*sc+sh);
    float b = lrelu(r0.y*sc+sh);
    float c2 = lrelu(r1.x*sc+sh);
    float d = lrelu(r1.y*sc+sh);
    dst[idx] = fmaxf(fmaxf(a,b), fmaxf(c2,d));
}

// ---------------- conv2 (bf16-split tensor core implicit GEMM) ---------------
// g_Bf (NCHW, 42x42) -> g_Cf (NCHW raw). Per block: image n, 16x16 output tile.
__global__ void __launch_bounds__(256,2) conv2_tc() {
    extern __shared__ float sm[];
    float* sIn = sm;                              // [18][18][18pad] floats
    uint32_t* sWh = (uint32_t*)(sm + 5832);       // [9][8][32][2]
    uint32_t* sWl = sWh + 4608;
    int n = blockIdx.y;
    int bx = blockIdx.x;                          // 0..8
    int x0 = (bx % 3) * 16, y0 = (bx / 3) * 16;
    int tid = threadIdx.x;
    int w = tid >> 5, lane = tid & 31, g = lane >> 2, q4 = lane & 3;
    float acc[2][8][4];
    #pragma unroll
    for (int i=0;i<2;i++)
      #pragma unroll
      for (int nt=0;nt<8;nt++)
        #pragma unroll
        for (int r=0;r<4;r++) acc[i][nt][r]=0.f;
    const float* ibase = g_Bf + (size_t)n*CH*H2*H2;
    for (int cc=0; cc<4; cc++) {
        __syncthreads();
        for (int i=tid; i<5184; i+=256) {
            int ci = i / 324, rem = i % 324, yy = rem / 18, xx = rem % 18;
            int gy = y0 - 1 + yy, gx = x0 - 1 + xx;
            float v = 0.f;
            if (gy>=0 && gy<H2 && gx>=0 && gx<H2)
                v = ibase[(size_t)(cc*16+ci)*H2*H2 + gy*H2 + gx];
            sIn[(yy*18 + xx)*18 + ci] = v;
        }
        {
            const uint4* sh = (const uint4*)(g_W2h + cc*4608);
            const uint4* sl = (const uint4*)(g_W2l + cc*4608);
            uint4* dh = (uint4*)sWh;
            uint4* dl = (uint4*)sWl;
            for (int i=tid; i<1152; i+=256) { dh[i]=sh[i]; dl[i]=sl[i]; }
        }
        __syncthreads();
        for (int s=0; s<9; s++) {
            int dy = s / 3, dx = s - 3*dy;
            uint32_t Ah[2][4], Al[2][4];
            #pragma unroll
            for (int i=0;i<2;i++) {
                int yy = 2*w + i + dy;
                const float* pl = &sIn[(yy*18 + (g + dx))*18];
                const float* ph = &sIn[(yy*18 + (g + 8 + dx))*18];
                float2 v0 = *(const float2*)(pl + 2*q4);
                float2 v1 = *(const float2*)(ph + 2*q4);
                float2 v2 = *(const float2*)(pl + 2*q4 + 8);
                float2 v3 = *(const float2*)(ph + 2*q4 + 8);
                split2(v0.x, v0.y, Ah[i][0], Al[i][0]);
                split2(v1.x, v1.y, Ah[i][1], Al[i][1]);
                split2(v2.x, v2.y, Ah[i][2], Al[i][2]);
                split2(v3.x, v3.y, Ah[i][3], Al[i][3]);
            }
            #pragma unroll
            for (int nt=0; nt<8; nt++) {
                int wb = s*512 + nt*64 + lane*2;
                uint32_t bh0 = sWh[wb], bh1 = sWh[wb+1];
                uint32_t bl0 = sWl[wb], bl1 = sWl[wb+1];
                #pragma unroll
                for (int i=0;i<2;i++) {
                    MMA_BF16(acc[i][nt], Ah[i], bh0, bh1);
                    MMA_BF16(acc[i][nt], Ah[i], bl0, bl1);
                    MMA_BF16(acc[i][nt], Al[i], bh0, bh1);
                }
            }
        }
    }
    #pragma unroll
    for (int i=0;i<2;i++) {
        int y = y0 + 2*w + i;
        if (y >= H2) continue;
        int xA = x0 + g, xB = x0 + g + 8;
        bool vB = (xB < H2);
        #pragma unroll
        for (int nt=0; nt<8; nt++) {
            int co = nt*8 + 2*q4;
            size_t p0 = ((size_t)(n*CH + co    )*H2 + y)*H2;
            size_t p1 = ((size_t)(n*CH + co + 1)*H2 + y)*H2;
            g_Cf[p0 + xA] = acc[i][nt][0];
            g_Cf[p1 + xA] = acc[i][nt][1];
            if (vB) {
                g_Cf[p0 + xB] = acc[i][nt][2];
                g_Cf[p1 + xB] = acc[i][nt][3];
            }
        }
    }
}

// ---------------- conv3/conv4 (bf16-split tensor core) @ 21x21 ---------------
// which 0: g_A -> g_Cf (no BN on read, weights W3)
// which 1: g_Cf -> g_Bf (apply BN3+lrelu on in-bounds read, weights W4)
// M = 441 positions padded to 448 = 28 m16-tiles; block = half (16 or 12 tiles).
__global__ void __launch_bounds__(256,2) conv34_tc(int which) {
    extern __shared__ float sm[];
    float* sIn = sm;                              // [23*23][16] = 8464 floats
    uint32_t* sWh = (uint32_t*)(sm + 8464);       // [9][8][32][2]
    uint32_t* sWl = sWh + 4608;
    const float* src = which ? g_Cf : g_A;
    float* dst = which ? g_Bf : g_Cf;
    int n = blockIdx.y;
    int half = blockIdx.x;
    int grp = (n < NQIMG) ? 0 : 1;
    int tid = threadIdx.x;
    int w = tid >> 5, lane = tid & 31, g = lane >> 2, q4 = lane & 3;
    float acc[2][8][4];
    #pragma unroll
    for (int i=0;i<2;i++)
      #pragma unroll
      for (int nt=0;nt<8;nt++)
        #pragma unroll
        for (int r=0;r<4;r++) acc[i][nt][r]=0.f;
    // per-warp m-tile indices and row->(y,x) precompute
    int tiles[2];
    tiles[0] = half*16 + w*2;
    tiles[1] = half*16 + w*2 + 1;
    int py[2][2], px[2][2];     // [tt][row: g | g+8]
    bool pv[2][2];
    #pragma unroll
    for (int tt=0;tt<2;tt++) {
        int p0 = tiles[tt]*16 + g;
        int p1 = tiles[tt]*16 + g + 8;
        pv[tt][0] = (tiles[tt] < 28) && (p0 < LL);
        pv[tt][1] = (tiles[tt] < 28) && (p1 < LL);
        py[tt][0] = p0 / 21; px[tt][0] = p0 % 21;
        py[tt][1] = p1 / 21; px[tt][1] = p1 % 21;
    }
    const float* ibase = src + (size_t)n*CH*LL;
    const uint32_t* Wh = which ? g_W4h : g_W3h;
    const uint32_t* Wl = which ? g_W4l : g_W3l;
    for (int cc=0; cc<4; cc++) {
        __syncthreads();
        // stage 23x23 halo, channel-last [pos][ci]; BN3 applied in-bounds only
        for (int i=tid; i<8464; i+=256) {
            int ci = i / 529, pos = i % 529;
            int yy = pos / 23, xx = pos % 23;
            int gy = yy - 1, gx = xx - 1;
            float v = 0.f;
            if (gy>=0 && gy<H3 && gx>=0 && gx<H3) {
                v = ibase[(size_t)(cc*16+ci)*LL + gy*21 + gx];
                if (which) v = lrelu(v*g_scale[grp*64+cc*16+ci] + g_shift[grp*64+cc*16+ci]);
            }
            sIn[pos*16 + ci] = v;
        }
        {
            const uint4* sh = (const uint4*)(Wh + cc*4608);
            const uint4* sl = (const uint4*)(Wl + cc*4608);
            uint4* dh = (uint4*)sWh;
            uint4* dl = (uint4*)sWl;
            for (int i=tid; i<1152; i+=256) { dh[i]=sh[i]; dl[i]=sl[i]; }
        }
        __syncthreads();
        for (int s=0; s<9; s++) {
            int dy = s / 3, dx = s - 3*dy;
            uint32_t Ah[2][4], Al[2][4];
            #pragma unroll
            for (int tt=0;tt<2;tt++) {
                float2 v0 = {0,0}, v1 = {0,0}, v2 = {0,0}, v3 = {0,0};
                if (pv[tt][0]) {
                    const float* p = &sIn[((py[tt][0]+dy)*23 + px[tt][0]+dx)*16];
                    v0 = *(const float2*)(p + 2*q4);
                    v2 = *(const float2*)(p + 2*q4 + 8);
                }
                if (pv[tt][1]) {
                    const float* p = &sIn[((py[tt][1]+dy)*23 + px[tt][1]+dx)*16];
                    v1 = *(const float2*)(p + 2*q4);
                    v3 = *(const float2*)(p + 2*q4 + 8);
                }
                split2(v0.x, v0.y, Ah[tt][0], Al[tt][0]);
                split2(v1.x, v1.y, Ah[tt][1], Al[tt][1]);
                split2(v2.x, v2.y, Ah[tt][2], Al[tt][2]);
                split2(v3.x, v3.y, Ah[tt][3], Al[tt][3]);
            }
            #pragma unroll
            for (int nt=0; nt<8; nt++) {
                int wb = s*512 + nt*64 + lane*2;
                uint32_t bh0 = sWh[wb], bh1 = sWh[wb+1];
                uint32_t bl0 = sWl[wb], bl1 = sWl[wb+1];
                #pragma unroll
                for (int tt=0;tt<2;tt++) {
                    MMA_BF16(acc[tt][nt], Ah[tt], bh0, bh1);
                    MMA_BF16(acc[tt][nt], Ah[tt], bl0, bl1);
                    MMA_BF16(acc[tt][nt], Al[tt], bh0, bh1);
                }
            }
        }
    }
    // store: rows g (c0,c1) and g+8 (c2,c3); cols co=nt*8+2q4, +1
    #pragma unroll
    for (int tt=0;tt<2;tt++) {
        int pA = tiles[tt]*16 + g;
        int pB = tiles[tt]*16 + g + 8;
        #pragma unroll
        for (int nt=0; nt<8; nt++) {
            int co = nt*8 + 2*q4;
            size_t b0 = ((size_t)n*CH + co    )*LL;
            size_t b1 = ((size_t)n*CH + co + 1)*LL;
            if (pv[tt][0]) {
                dst[b0 + pA] = acc[tt][nt][0];
                dst[b1 + pA] = acc[tt][nt][1];
            }
            if (pv[tt][1]) {
                dst[b0 + pB] = acc[tt][nt][2];
                dst[b1 + pB] = acc[tt][nt][3];
            }
        }
    }
}

// ---------------- BN4 + LReLU + L2-normalize + tf32-round + transpose --------
__global__ void normalize_kernel() {
    int n = blockIdx.y;
    int l = blockIdx.x*256 + threadIdx.x;
    if (l >= LL) return;
    int grp = (n < NQIMG) ? 0 : 1;
    float v[64];
    float ss = 0.f;
    const float* p = g_Bf + (size_t)n*CH*LL + l;
    #pragma unroll
    for (int c=0;c<64;c++) {
        float t = lrelu(p[(size_t)c*LL]*g_scale[grp*64+c] + g_shift[grp*64+c]);
        v[c] = t; ss += t*t;
    }
    float inv = 1.f / fmaxf(sqrtf(ss), 1e-12f);
    float* dstp;
    if (n < NQIMG) {
        dstp = &g_qn[((size_t)n*LL + l)*64];
    } else {
        int ns = n - NQIMG;
        int b = ns/25, w = (ns%25)/5, s = ns%5;
        dstp = &g_sn[(((size_t)(b*5+w))*MM + (size_t)s*LL + l)*64];
    }
    #pragma unroll
    for (int c=0;c<64;c++) {
        float o = v[c]*inv;
        uint32_t ot;
        asm("cvt.rna.tf32.f32 %0, %1;" : "=r"(ot) : "f"(o));
        dstp[c] = __uint_as_float(ot);
    }
}

// ---------------- similarity: tf32 mma + top-3 + sum ----------------
__global__ void __launch_bounds__(256) sim_kernel(float* __restrict__ out) {
    __shared__ float sQ[64*68];
    __shared__ float sS[64*68];
    __shared__ float smerge[64][2][3];
    __shared__ float bsum;
    int lt = blockIdx.x;
    int bc = blockIdx.y;
    int b = bc/80; int q = (bc/5)%16; int c = bc%5;
    const float* qb = g_qn + ((size_t)(b*16+q))*LL*64;
    const float* sb = g_sn + ((size_t)(b*5+c))*MM*64;
    int tid = threadIdx.x;
    int w = tid >> 5, lane = tid & 31;
    int g = lane >> 2, q4 = lane & 3;
    int rg = w & 3, cg = w >> 2;
    {
        int row = tid >> 2; int col = (tid & 3) << 4;
        int grow = lt*64 + row;
        float4* d4 = (float4*)&sQ[row*68 + col];
        if (grow < LL) {
            const float4* s4 = (const float4*)(qb + (size_t)grow*64 + col);
            d4[0]=s4[0]; d4[1]=s4[1]; d4[2]=s4[2]; d4[3]=s4[3];
        } else {
            float4 z = {0,0,0,0};
            d4[0]=z; d4[1]=z; d4[2]=z; d4[3]=z;
        }
    }
    if (tid==0) bsum = 0.f;
    __syncthreads();
    int r0 = rg*16;
    unsigned afr[8][4];
    {
        const float* qa = &sQ[(r0+g)*68 + q4];
        #pragma unroll
        for (int kc=0;kc<8;kc++) {
            afr[kc][0] = __float_as_uint(qa[kc*8]);
            afr[kc][1] = __float_as_uint(qa[8*68 + kc*8]);
            afr[kc][2] = __float_as_uint(qa[kc*8 + 4]);
            afr[kc][3] = __float_as_uint(qa[8*68 + kc*8 + 4]);
        }
    }
    float a0=-1e30f,a1=-1e30f,a2=-1e30f;
    float b0_=-1e30f,b1_=-1e30f,b2_=-1e30f;
    int n0 = cg*32;
    for (int mt=0; mt<35; mt++) {
        __syncthreads();
        {
            int row = tid >> 2; int col = (tid & 3) << 4;
            int m = mt*64 + row;
            float4* d4 = (float4*)&sS[row*68 + col];
            if (m < MM) {
                const float4* s4 = (const float4*)(sb + (size_t)m*64 + col);
                d4[0]=s4[0]; d4[1]=s4[1]; d4[2]=s4[2]; d4[3]=s4[3];
            } else {
                float4 z = {0,0,0,0};
                d4[0]=z; d4[1]=z; d4[2]=z; d4[3]=z;
            }
        }
        __syncthreads();
        bool tail = (mt == 34);
        #pragma unroll
        for (int nt=0; nt<4; nt++) {
            float c0f=0.f, c1f=0.f, c2f=0.f, c3f=0.f;
            const float* pB = &sS[(n0 + nt*8 + g)*68 + q4];
            #pragma unroll
            for (int kc=0;kc<8;kc++) {
                unsigned bb0 = __float_as_uint(pB[kc*8]);
                unsigned bb1 = __float_as_uint(pB[kc*8 + 4]);
                asm volatile(
                  "mma.sync.aligned.m16n8k8.row.col.f32.tf32.tf32.f32 "
                  "{%0,%1,%2,%3},{%4,%5,%6,%7},{%8,%9},{%0,%1,%2,%3};"
                  : "+f"(c0f), "+f"(c1f), "+f"(c2f), "+f"(c3f)
                  : "r"(afr[kc][0]), "r"(afr[kc][1]), "r"(afr[kc][2]), "r"(afr[kc][3]),
                    "r"(bb0), "r"(bb1));
            }
            if (tail) {
                int col0 = mt*64 + n0 + nt*8 + (q4<<1);
                if (col0   < MM) { ins3(c0f, a0,a1,a2); ins3(c2f, b0_,b1_,b2_); }
                if (col0+1 < MM) { ins3(c1f, a0,a1,a2); ins3(c3f, b0_,b1_,b2_); }
            } else {
                ins3(c0f, a0,a1,a2); ins3(c1f, a0,a1,a2);
                ins3(c2f, b0_,b1_,b2_); ins3(c3f, b0_,b1_,b2_);
            }
        }
    }
    #pragma unroll
    for (int ofs=1; ofs<=2; ofs<<=1) {
        float o0 = __shfl_xor_sync(0xffffffffu, a0, ofs);
        float o1 = __shfl_xor_sync(0xffffffffu, a1, ofs);
        float o2 = __shfl_xor_sync(0xffffffffu, a2, ofs);
        ins3(o0, a0,a1,a2); ins3(o1, a0,a1,a2); ins3(o2, a0,a1,a2);
        o0 = __shfl_xor_sync(0xffffffffu, b0_, ofs);
        o1 = __shfl_xor_sync(0xffffffffu, b1_, ofs);
        o2 = __shfl_xor_sync(0xffffffffu, b2_, ofs);
        ins3(o0, b0_,b1_,b2_); ins3(o1, b0_,b1_,b2_); ins3(o2, b0_,b1_,b2_);
    }
    if (q4 == 0) {
        int rA = r0 + g;
        smerge[rA][cg][0]=a0; smerge[rA][cg][1]=a1; smerge[rA][cg][2]=a2;
        smerge[rA+8][cg][0]=b0_; smerge[rA+8][cg][1]=b1_; smerge[rA+8][cg][2]=b2_;
    }
    __syncthreads();
    if (tid < 64) {
        float m0 = smerge[tid][0][0], m1 = smerge[tid][0][1], m2 = smerge[tid][0][2];
        ins3(smerge[tid][1][0], m0,m1,m2);
        ins3(smerge[tid][1][1], m0,m1,m2);
        ins3(smerge[tid][1][2], m0,m1,m2);
        int grow = lt*64 + tid;
        if (grow < LL) atomicAdd(&bsum, m0+m1+m2);
    }
    __syncthreads();
    if (tid==0) atomicAdd(&out[(b*16+q)*5 + c], bsum);
}

// ---------------- launcher ----------------
extern "C" void kernel_launch(void* const* d_in, const int* in_sizes, int n_in,
                              void* d_out, int out_size) {
    const float* query   = (const float*)d_in[0];
    const float* support = (const float*)d_in[1];
    const float* W1 = (const float*)d_in[2];
    const float* g1 = (const float*)d_in[3];
    const float* b1 = (const float*)d_in[4];
    const float* W2 = (const float*)d_in[5];
    const float* g2 = (const float*)d_in[6];
    const float* b2 = (const float*)d_in[7];
    const float* W3 = (const float*)d_in[8];
    const float* g3 = (const float*)d_in[9];
    const float* b3 = (const float*)d_in[10];
    const float* W4 = (const float*)d_in[11];
    const float* g4 = (const float*)d_in[12];
    const float* b4 = (const float*)d_in[13];
    float* out = (float*)d_out;

    cudaFuncSetAttribute(conv2_tc, cudaFuncAttributeMaxDynamicSharedMemorySize, 60192);
    cudaFuncSetAttribute(conv34_tc, cudaFuncAttributeMaxDynamicSharedMemorySize, 70720);

    zero_kernel<<<1, 256>>>(out);

    // weight prep
    wtrans_kernel<<<7, 256>>>(W1, 3);
    wfrag_kernel<<<72, 256>>>(W2, 2);
    wfrag_kernel<<<72, 256>>>(W3, 3);
    wfrag_kernel<<<72, 256>>>(W4, 4);

    // block 1: conv1 -> g_A -> (stats) -> pool -> g_Bf
    conv1_kernel<<<dim3(36,2,NIMG), 256>>>(query, support);
    bn_part_kernel<<<dim3(128,8), 256>>>(0, H1*H1);
    bn_fin_kernel<<<1, 128>>>(H1*H1, g1, b1);
    {
        long long tot = (long long)NIMG*CH*H2*H2;
        bn_pool_kernel<<<(unsigned)((tot+255)/256), 256>>>(0, H1);
    }
    // block 2: g_Bf -> g_Cf (tensor cores) -> (stats) -> pool -> g_A
    conv2_tc<<<dim3(9,NIMG), 256, 60192>>>();
    bn_part_kernel<<<dim3(128,8), 256>>>(2, H2*H2);
    bn_fin_kernel<<<1, 128>>>(H2*H2, g2, b2);
    {
        long long tot = (long long)NIMG*CH*H3*H3;
        bn_pool_kernel<<<(unsigned)((tot+255)/256), 256>>>(1, H2);
    }
    // block 3: g_A -> g_Cf (tensor cores, raw) -> stats3
    conv34_tc<<<dim3(2,NIMG), 256, 70720>>>(0);
    bn_part_kernel<<<dim3(128,8), 256>>>(2, LL);
    bn_fin_kernel<<<1, 128>>>(LL, g3, b3);
    // block 4: g_Cf (apply BN3 on read) -> g_Bf (tensor cores) -> stats4 -> normalize
    conv34_tc<<<dim3(2,NIMG), 256, 70720>>>(1);
    bn_part_kernel<<<dim3(128,8), 256>>>(1, LL);
    bn_fin_kernel<<<1, 128>>>(LL, g4, b4);
    normalize_kernel<<<dim3(2,NIMG), 256>>>();

    // cosine sim (tf32 tensor cores) + top-3 + sum
    sim_kernel<<<dim3(7,160), 256>>>(out);
}

// round 9
// speedup vs baseline: 4.0151x; 1.1298x over previous
#include <cuda_runtime.h>
#include <cuda_bf16.h>
#include <cstdint>

#define LRELU_SLOPE 0.2f
#define BN_EPS 1e-5f

#define NIMG 82
#define NQIMG 32
#define CH 64
#define H1 84
#define H2 42
#define H3 21
#define LL 441
#define MM 2205

// ---------------- scratch (device globals; no allocs allowed) ----------------
__device__ float g_A[(size_t)NIMG*CH*H1*H1];
__device__ float g_Bf[(size_t)NIMG*CH*H2*H2];
__device__ float g_Cf[(size_t)NIMG*CH*H2*H2];
__device__ float g_qn[(size_t)NQIMG*LL*CH];
__device__ float g_sn[(size_t)2*5*MM*CH];
__device__ float g_bnsum4[4*128*2];            // [layer][grp*64+c][{s,s2}]
__device__ float g_WT[64*9*64];                // conv1 weights [ci*9+k][co]
// bf16-split weight fragments: [cc(4)][s(9)][nt(8)][lane(32)][reg(2)]
__device__ uint32_t g_W2h[18432];
__device__ uint32_t g_W2l[18432];
__device__ uint32_t g_W3h[18432];
__device__ uint32_t g_W3l[18432];
__device__ uint32_t g_W4h[18432];
__device__ uint32_t g_W4l[18432];

__device__ __forceinline__ float lrelu(float x){ return x >= 0.f ? x : LRELU_SLOPE*x; }

__device__ __forceinline__ void ins3(float v, float& t0, float& t1, float& t2){
    if (v > t2) {
        float s  = fminf(t0, v);
        t0 = fmaxf(t0, v);
        float s2 = fminf(t1, s);
        t1 = fmaxf(t1, s);
        t2 = fmaxf(t2, s2);
    }
}

// split fp32 pair into bf16x2 hi + bf16x2 lo (v = hi + lo, error ~2^-18)
__device__ __forceinline__ void split2(float vx, float vy, uint32_t& hi, uint32_t& lo){
    __nv_bfloat162 h = __floats2bfloat162_rn(vx, vy);
    float hx = __bfloat162float(h.x);
    float hy = __bfloat162float(h.y);
    __nv_bfloat162 l = __floats2bfloat162_rn(vx - hx, vy - hy);
    hi = *reinterpret_cast<uint32_t*>(&h);
    lo = *reinterpret_cast<uint32_t*>(&l);
}

#define MMA_BF16(C, A, b0, b1) \
    asm volatile("mma.sync.aligned.m16n8k16.row.col.f32.bf16.bf16.f32 " \
        "{%0,%1,%2,%3},{%4,%5,%6,%7},{%8,%9},{%0,%1,%2,%3};" \
        : "+f"((C)[0]), "+f"((C)[1]), "+f"((C)[2]), "+f"((C)[3]) \
        : "r"((A)[0]), "r"((A)[1]), "r"((A)[2]), "r"((A)[3]), "r"(b0), "r"(b1))

#define MMA_TF32(C, A, b0, b1) \
    asm volatile("mma.sync.aligned.m16n8k8.row.col.f32.tf32.tf32.f32 " \
        "{%0,%1,%2,%3},{%4,%5,%6,%7},{%8,%9},{%0,%1,%2,%3};" \
        : "+f"((C)[0]), "+f"((C)[1]), "+f"((C)[2]), "+f"((C)[3]) \
        : "r"((A)[0]), "r"((A)[1]), "r"((A)[2]), "r"((A)[3]), "r"(b0), "r"(b1))

// BN scale/shift from per-layer raw sums
__device__ __forceinline__ void bn_sc(int layer, int gc, float HW, float gamma, float beta,
                                      float& sc, float& sh){
    float s  = g_bnsum4[(layer*128 + gc)*2 + 0];
    float s2 = g_bnsum4[(layer*128 + gc)*2 + 1];
    float cnt = ((gc >= 64) ? 50.f : 32.f) * HW;
    float mean = s / cnt;
    float var = s2 / cnt - mean*mean;
    float inv = rsqrtf(var + BN_EPS);
    sc = gamma * inv;
    sh = beta - mean * sc;
}

// ---------------- prep: zero + conv1 wtrans + conv2/3/4 frag pack ------------
__device__ __forceinline__ void frag_compute(const float* __restrict__ W, int i,
                                             uint32_t& hi, uint32_t& lo){
    int r  = i & 1;
    int t  = (i >> 1) & 31;
    int nt = (i >> 6) & 7;
    int rem = i >> 9;          // 0..35
    int s  = rem % 9;
    int cc = rem / 9;
    int q = t & 3, nn = t >> 2;
    int ci = cc*16 + 2*q + 8*r;
    int co = nt*8 + nn;
    float v0 = W[((size_t)co*64 + ci    )*9 + s];
    float v1 = W[((size_t)co*64 + ci + 1)*9 + s];
    split2(v0, v1, hi, lo);
}

__global__ void prep_kernel(float* out, const float* __restrict__ W1,
                            const float* __restrict__ W2, const float* __restrict__ W3,
                            const float* __restrict__ W4){
    int bx = blockIdx.x, tid = threadIdx.x;
    if (bx == 0) {
        if (tid < 160) out[tid] = 0.f;
        for (int i = tid; i < 4*128*2; i += 256) g_bnsum4[i] = 0.f;
    } else if (bx < 8) {
        int i = (bx-1)*256 + tid;
        if (i < 3*9*64) {
            int co = i & 63, r = i >> 6;
            int ci = r / 9, k = r % 9;
            g_WT[i] = W1[(size_t)co*3*9 + ci*9 + k];
        }
    } else if (bx < 80) {
        int i = (bx-8)*256 + tid;
        uint32_t hi, lo; frag_compute(W2, i, hi, lo);
        g_W2h[i] = hi; g_W2l[i] = lo;
    } else if (bx < 152) {
        int i = (bx-80)*256 + tid;
        uint32_t hi, lo; frag_compute(W3, i, hi, lo);
        g_W3h[i] = hi; g_W3l[i] = lo;
    } else {
        int i = (bx-152)*256 + tid;
        uint32_t hi, lo; frag_compute(W4, i, hi, lo);
        g_W4h[i] = hi; g_W4l[i] = lo;
    }
}

// ---------------- conv1: 3->64 @ 84x84, pad 1 (writes g_A) ----------------
__global__ void __launch_bounds__(256,3) conv1_kernel(const float* __restrict__ query,
                                                      const float* __restrict__ support) {
    __shared__ float swt[27*32];
    __shared__ float sin[3*18*18];
    int n = blockIdx.z, coH = blockIdx.y;
    int bx = blockIdx.x;
    int x0 = (bx % 6) * 16, y0 = (bx / 6) * 16;
    int tid = threadIdx.x;
    int tx = tid & 15, ty = tid >> 4;
    for (int i = tid; i < 864; i += 256) {
        int kk = i >> 5, co = i & 31;
        swt[i] = g_WT[kk*64 + coH*32 + co];
    }
    const float* img = (n < NQIMG) ? (query + (size_t)n*3*H1*H1)
                                   : (support + (size_t)(n-NQIMG)*3*H1*H1);
    for (int i = tid; i < 972; i += 256) {
        int ci = i / 324, rem = i % 324;
        int yy = rem / 18, xx = rem % 18;
        int gy = y0 - 1 + yy, gx = x0 - 1 + xx;
        sin[i] = (gy>=0 && gy<H1 && gx>=0 && gx<H1) ? img[(size_t)ci*H1*H1 + gy*H1 + gx] : 0.f;
    }
    __syncthreads();
    float r[27];
    #pragma unroll
    for (int ci=0;ci<3;ci++)
      #pragma unroll
      for (int dy=0;dy<3;dy++)
        #pragma unroll
        for (int dx=0;dx<3;dx++)
          r[ci*9+dy*3+dx] = sin[ci*324 + (ty+dy)*18 + (tx+dx)];
    float acc[32];
    #pragma unroll
    for (int i=0;i<32;i++) acc[i]=0.f;
    const float4* swt4 = (const float4*)swt;
    #pragma unroll
    for (int kk=0; kk<27; kk++) {
        float v = r[kk];
        #pragma unroll
        for (int c4=0; c4<8; c4++) {
            float4 w = swt4[kk*8 + c4];
            acc[c4*4+0] += w.x*v;
            acc[c4*4+1] += w.y*v;
            acc[c4*4+2] += w.z*v;
            acc[c4*4+3] += w.w*v;
        }
    }
    int y = y0+ty, x = x0+tx;
    if (y < H1 && x < H1) {
        size_t obase = ((size_t)n*CH + coH*32)*H1*H1 + (size_t)y*H1 + x;
        #pragma unroll 4
        for (int co=0; co<32; co++) g_A[obase + (size_t)co*H1*H1] = acc[co];
    }
}

// ---------------- BN partial stats -> g_bnsum4[layer] ----------------
__global__ void bn_part_kernel(int srcSel, int HW, int layer){
    const float* src = (srcSel==0) ? g_A : (srcSel==1) ? g_Bf : g_Cf;
    int gc = blockIdx.x;
    int grp = gc >> 6, c = gc & 63;
    int slice = blockIdx.y;
    int n0, n1;
    if (!grp) { n0 = slice*4; n1 = n0+4; }
    else { n0 = 32 + (50*slice)/8; n1 = 32 + (50*(slice+1))/8; }
    float s = 0.f, s2 = 0.f;
    if ((HW & 3) == 0) {
        int m = HW >> 2;
        for (int n=n0; n<n1; n++) {
            const float4* p = (const float4*)(src + ((size_t)n*CH + c)*HW);
            for (int i=threadIdx.x; i<m; i+=256) {
                float4 v = p[i];
                s  += v.x + v.y + v.z + v.w;
                s2 += v.x*v.x + v.y*v.y + v.z*v.z + v.w*v.w;
            }
        }
    } else {
        for (int n=n0; n<n1; n++) {
            const float* p = src + ((size_t)n*CH + c)*HW;
            for (int i=threadIdx.x; i<HW; i+=256) {
                float v = p[i]; s += v; s2 += v*v;
            }
        }
    }
    __shared__ float sh1[256], sh2[256];
    sh1[threadIdx.x]=s; sh2[threadIdx.x]=s2;
    __syncthreads();
    for (int ofs=128; ofs>0; ofs>>=1) {
        if (threadIdx.x<ofs){ sh1[threadIdx.x]+=sh1[threadIdx.x+ofs]; sh2[threadIdx.x]+=sh2[threadIdx.x+ofs]; }
        __syncthreads();
    }
    if (threadIdx.x==0) {
        atomicAdd(&g_bnsum4[(layer*128+gc)*2+0], sh1[0]);
        atomicAdd(&g_bnsum4[(layer*128+gc)*2+1], sh2[0]);
    }
}

// ---------------- BN + LReLU + 2x2 maxpool (inline scale) ----------------
// dir 0: g_A -> g_Bf (Hi=84, layer0); dir 1: g_Cf -> g_A (Hi=42, layer1)
__global__ void bn_pool_kernel(int dir, int Hi, const float* __restrict__ gamma,
                               const float* __restrict__ beta, int layer) {
    const float* src = dir ? g_Cf : g_A;
    float* dst = dir ? g_A : g_Bf;
    int Ho = Hi >> 1;
    long long total = (long long)NIMG*CH*Ho*Ho;
    long long idx = (long long)blockIdx.x*blockDim.x + threadIdx.x;
    if (idx >= total) return;
    int x = (int)(idx % Ho); long long t = idx / Ho;
    int y = (int)(t % Ho); t /= Ho;
    int c = (int)(t & 63); int n = (int)(t >> 6);
    int grp = (n < NQIMG) ? 0 : 1;
    float sc, sh;
    bn_sc(layer, grp*64+c, (float)(Hi*Hi), gamma[c], beta[c], sc, sh);
    const float* p = src + (((size_t)n*CH + c)*Hi + 2*y)*Hi + 2*x;
    float2 r0 = *(const float2*)p;
    float2 r1 = *(const float2*)(p + Hi);
    float a = lrelu(r0.x*sc+sh);
    float b = lrelu(r0.y*sc+sh);
    float c2 = lrelu(r1.x*sc+sh);
    float d = lrelu(r1.y*sc+sh);
    dst[idx] = fmaxf(fmaxf(a,b), fmaxf(c2,d));
}

// ---------------- conv2 (bf16-split tensor core implicit GEMM) ---------------
__global__ void __launch_bounds__(256,2) conv2_tc() {
    extern __shared__ float sm[];
    float* sIn = sm;                              // 5832
    uint32_t* sWh = (uint32_t*)(sm + 5832);       // 4608
    uint32_t* sWl = sWh + 4608;
    int n = blockIdx.y;
    int bx = blockIdx.x;
    int x0 = (bx % 3) * 16, y0 = (bx / 3) * 16;
    int tid = threadIdx.x;
    int w = tid >> 5, lane = tid & 31, g = lane >> 2, q4 = lane & 3;
    float acc[2][8][4];
    #pragma unroll
    for (int i=0;i<2;i++)
      #pragma unroll
      for (int nt=0;nt<8;nt++)
        #pragma unroll
        for (int r=0;r<4;r++) acc[i][nt][r]=0.f;
    const float* ibase = g_Bf + (size_t)n*CH*H2*H2;
    for (int cc=0; cc<4; cc++) {
        __syncthreads();
        for (int i=tid; i<5184; i+=256) {
            int ci = i / 324, rem = i % 324, yy = rem / 18, xx = rem % 18;
            int gy = y0 - 1 + yy, gx = x0 - 1 + xx;
            float v = 0.f;
            if (gy>=0 && gy<H2 && gx>=0 && gx<H2)
                v = ibase[(size_t)(cc*16+ci)*H2*H2 + gy*H2 + gx];
            sIn[(yy*18 + xx)*18 + ci] = v;
        }
        {
            const uint4* sh = (const uint4*)(g_W2h + cc*4608);
            const uint4* sl = (const uint4*)(g_W2l + cc*4608);
            uint4* dh = (uint4*)sWh;
            uint4* dl = (uint4*)sWl;
            for (int i=tid; i<1152; i+=256) { dh[i]=sh[i]; dl[i]=sl[i]; }
        }
        __syncthreads();
        for (int s=0; s<9; s++) {
            int dy = s / 3, dx = s - 3*dy;
            uint32_t Ah[2][4], Al[2][4];
            #pragma unroll
            for (int i=0;i<2;i++) {
                int yy = 2*w + i + dy;
                const float* pl = &sIn[(yy*18 + (g + dx))*18];
                const float* ph = &sIn[(yy*18 + (g + 8 + dx))*18];
                float2 v0 = *(const float2*)(pl + 2*q4);
                float2 v1 = *(const float2*)(ph + 2*q4);
                float2 v2 = *(const float2*)(pl + 2*q4 + 8);
                float2 v3 = *(const float2*)(ph + 2*q4 + 8);
                split2(v0.x, v0.y, Ah[i][0], Al[i][0]);
                split2(v1.x, v1.y, Ah[i][1], Al[i][1]);
                split2(v2.x, v2.y, Ah[i][2], Al[i][2]);
                split2(v3.x, v3.y, Ah[i][3], Al[i][3]);
            }
            #pragma unroll
            for (int nt=0; nt<8; nt++) {
                int wb = s*512 + nt*64 + lane*2;
                uint32_t bh0 = sWh[wb], bh1 = sWh[wb+1];
                uint32_t bl0 = sWl[wb], bl1 = sWl[wb+1];
                #pragma unroll
                for (int i=0;i<2;i++) {
                    MMA_BF16(acc[i][nt], Ah[i], bh0, bh1);
                    MMA_BF16(acc[i][nt], Ah[i], bl0, bl1);
                    MMA_BF16(acc[i][nt], Al[i], bh0, bh1);
                }
            }
        }
    }
    #pragma unroll
    for (int i=0;i<2;i++) {
        int y = y0 + 2*w + i;
        if (y >= H2) continue;
        int xA = x0 + g, xB = x0 + g + 8;
        bool vB = (xB < H2);
        #pragma unroll
        for (int nt=0; nt<8; nt++) {
            int co = nt*8 + 2*q4;
            size_t p0 = ((size_t)(n*CH + co    )*H2 + y)*H2;
            size_t p1 = ((size_t)(n*CH + co + 1)*H2 + y)*H2;
            g_Cf[p0 + xA] = acc[i][nt][0];
            g_Cf[p1 + xA] = acc[i][nt][1];
            if (vB) {
                g_Cf[p0 + xB] = acc[i][nt][2];
                g_Cf[p1 + xB] = acc[i][nt][3];
            }
        }
    }
}

// ---------------- conv3/conv4 (bf16-split TC) @ 21x21, 1 tile/warp -----------
// which 0: g_A -> g_Cf (weights W3); which 1: g_Cf -> g_Bf (BN L2 on read, W4)
// grid (4, NIMG); warp w handles m-tile quarter*7+w (w<7).
__global__ void __launch_bounds__(256,3) conv34_tc(int which, const float* __restrict__ gamma,
                                                   const float* __restrict__ beta) {
    extern __shared__ float sm[];
    float* sIn = sm;                              // 8464
    uint32_t* sWh = (uint32_t*)(sm + 8464);       // 4608
    uint32_t* sWl = sWh + 4608;
    float* sc3 = (float*)(sWl + 4608);            // 64
    float* sh3 = sc3 + 64;                        // 64
    const float* src = which ? g_Cf : g_A;
    float* dst = which ? g_Bf : g_Cf;
    int n = blockIdx.y;
    int quarter = blockIdx.x;
    int grp = (n < NQIMG) ? 0 : 1;
    int tid = threadIdx.x;
    int w = tid >> 5, lane = tid & 31, g = lane >> 2, q4 = lane & 3;
    if (which && tid < 64) {
        float a, b;
        bn_sc(2, grp*64+tid, (float)LL, gamma[tid], beta[tid], a, b);
        sc3[tid] = a; sh3[tid] = b;
    }
    int t = quarter*7 + w;
    bool wact = (w < 7);
    int p0 = t*16 + g, p1 = p0 + 8;
    bool pv0 = wact && (p0 < LL), pv1 = wact && (p1 < LL);
    int py0 = p0/21, px0 = p0%21, py1 = p1/21, px1 = p1%21;
    float acc[8][4];
    #pragma unroll
    for (int nt=0;nt<8;nt++)
      #pragma unroll
      for (int r=0;r<4;r++) acc[nt][r]=0.f;
    const float* ibase = src + (size_t)n*CH*LL;
    const uint32_t* Wh = which ? g_W4h : g_W3h;
    const uint32_t* Wl = which ? g_W4l : g_W3l;
    for (int cc=0; cc<4; cc++) {
        __syncthreads();
        for (int i=tid; i<8464; i+=256) {
            int ci = i / 529, pos = i % 529;
            int yy = pos / 23, xx = pos % 23;
            int gy = yy - 1, gx = xx - 1;
            float v = 0.f;
            if (gy>=0 && gy<H3 && gx>=0 && gx<H3) {
                v = ibase[(size_t)(cc*16+ci)*LL + gy*21 + gx];
                if (which) v = lrelu(v*sc3[cc*16+ci] + sh3[cc*16+ci]);
            }
            sIn[pos*16 + ci] = v;
        }
        {
            const uint4* sh = (const uint4*)(Wh + cc*4608);
            const uint4* sl = (const uint4*)(Wl + cc*4608);
            uint4* dh = (uint4*)sWh;
            uint4* dl = (uint4*)sWl;
            for (int i=tid; i<1152; i+=256) { dh[i]=sh[i]; dl[i]=sl[i]; }
        }
        __syncthreads();
        if (wact) {
            for (int s=0; s<9; s++) {
                int dy = s / 3, dx = s - 3*dy;
                uint32_t Ah[4], Al[4];
                {
                    float2 v0 = {0,0}, v1 = {0,0}, v2 = {0,0}, v3 = {0,0};
                    if (pv0) {
                        const float* p = &sIn[((py0+dy)*23 + px0+dx)*16];
                        v0 = *(const float2*)(p + 2*q4);
                        v2 = *(const float2*)(p + 2*q4 + 8);
                    }
                    if (pv1) {
                        const float* p = &sIn[((py1+dy)*23 + px1+dx)*16];
                        v1 = *(const float2*)(p + 2*q4);
                        v3 = *(const float2*)(p + 2*q4 + 8);
                    }
                    split2(v0.x, v0.y, Ah[0], Al[0]);
                    split2(v1.x, v1.y, Ah[1], Al[1]);
                    split2(v2.x, v2.y, Ah[2], Al[2]);
                    split2(v3.x, v3.y, Ah[3], Al[3]);
                }
                #pragma unroll
                for (int nt=0; nt<8; nt++) {
                    int wb = s*512 + nt*64 + lane*2;
                    uint32_t bh0 = sWh[wb], bh1 = sWh[wb+1];
                    uint32_t bl0 = sWl[wb], bl1 = sWl[wb+1];
                    MMA_BF16(acc[nt], Ah, bh0, bh1);
                    MMA_BF16(acc[nt], Ah, bl0, bl1);
                    MMA_BF16(acc[nt], Al, bh0, bh1);
                }
            }
        }
    }
    #pragma unroll
    for (int nt=0; nt<8; nt++) {
        int co = nt*8 + 2*q4;
        size_t b0 = ((size_t)n*CH + co    )*LL;
        size_t b1 = ((size_t)n*CH + co + 1)*LL;
        if (pv0) {
            dst[b0 + p0] = acc[nt][0];
            dst[b1 + p0] = acc[nt][1];
        }
        if (pv1) {
            dst[b0 + p1] = acc[nt][2];
            dst[b1 + p1] = acc[nt][3];
        }
    }
}

// ---------------- BN4 + LReLU + L2-normalize + tf32-round + transpose --------
__global__ void normalize_kernel(const float* __restrict__ gamma, const float* __restrict__ beta) {
    __shared__ float sc4[64], sh4[64];
    int n = blockIdx.y;
    int grp = (n < NQIMG) ? 0 : 1;
    if (threadIdx.x < 64) {
        float a, b;
        bn_sc(3, grp*64+threadIdx.x, (float)LL, gamma[threadIdx.x], beta[threadIdx.x], a, b);
        sc4[threadIdx.x] = a; sh4[threadIdx.x] = b;
    }
    __syncthreads();
    int l = blockIdx.x*256 + threadIdx.x;
    if (l >= LL) return;
    float v[64];
    float ss = 0.f;
    const float* p = g_Bf + (size_t)n*CH*LL + l;
    #pragma unroll
    for (int c=0;c<64;c++) {
        float t = lrelu(p[(size_t)c*LL]*sc4[c] + sh4[c]);
        v[c] = t; ss += t*t;
    }
    float inv = 1.f / fmaxf(sqrtf(ss), 1e-12f);
    float* dstp;
    if (n < NQIMG) {
        dstp = &g_qn[((size_t)n*LL + l)*64];
    } else {
        int ns = n - NQIMG;
        int b = ns/25, w = (ns%25)/5, s = ns%5;
        dstp = &g_sn[(((size_t)(b*5+w))*MM + (size_t)s*LL + l)*64];
    }
    #pragma unroll
    for (int c=0;c<64;c++) {
        float o = v[c]*inv;
        uint32_t ot;
        asm("cvt.rna.tf32.f32 %0, %1;" : "=r"(ot) : "f"(o));
        dstp[c] = __uint_as_float(ot);
    }
}

// ---------------- similarity: tf32 mma, 2 queries/block ----------------
// grid (7 l-tiles, 80 (b,qpair,way)); 256 thr. Block tile 64L x 64M x 2 queries.
__global__ void __launch_bounds__(256,2) sim_kernel(float* __restrict__ out) {
    extern __shared__ float smem[];
    float* sQ  = smem;            // 2*64*68 = 8704
    float* sS  = sQ + 8704;       // 64*68 = 4352
    float* smg = sS + 4352;       // 2*64*2*3 = 768
    float* bs  = smg + 768;       // 2
    int lt = blockIdx.x;
    int bc = blockIdx.y;
    int b = bc/40; int qp = (bc/5)%8; int c = bc%5;
    const float* sb = g_sn + ((size_t)(b*5+c))*MM*64;
    int tid = threadIdx.x;
    int w = tid >> 5, lane = tid & 31;
    int g = lane >> 2, q4 = lane & 3;
    int rg = w & 3, cg = w >> 2;
    #pragma unroll
    for (int qq=0; qq<2; qq++) {
        const float* qb = g_qn + ((size_t)(b*16 + qp*2 + qq))*LL*64;
        int row = tid >> 2; int col = (tid & 3) << 4;
        int grow = lt*64 + row;
        float4* d4 = (float4*)&sQ[qq*4352 + row*68 + col];
        if (grow < LL) {
            const float4* s4 = (const float4*)(qb + (size_t)grow*64 + col);
            d4[0]=s4[0]; d4[1]=s4[1]; d4[2]=s4[2]; d4[3]=s4[3];
        } else {
            float4 z = {0,0,0,0};
            d4[0]=z; d4[1]=z; d4[2]=z; d4[3]=z;
        }
    }
    if (tid < 2) bs[tid] = 0.f;
    __syncthreads();
    int r0 = rg*16;
    unsigned afr[2][8][4];
    #pragma unroll
    for (int qq=0; qq<2; qq++) {
        const float* qa = &sQ[qq*4352 + (r0+g)*68 + q4];
        #pragma unroll
        for (int kc=0;kc<8;kc++) {
            afr[qq][kc][0] = __float_as_uint(qa[kc*8]);
            afr[qq][kc][1] = __float_as_uint(qa[8*68 + kc*8]);
            afr[qq][kc][2] = __float_as_uint(qa[kc*8 + 4]);
            afr[qq][kc][3] = __float_as_uint(qa[8*68 + kc*8 + 4]);
        }
    }
    float top[2][2][3];
    #pragma unroll
    for (int qq=0;qq<2;qq++)
      #pragma unroll
      for (int h=0;h<2;h++)
        #pragma unroll
        for (int k=0;k<3;k++) top[qq][h][k] = -1e30f;
    int n0 = cg*32;
    for (int mt=0; mt<35; mt++) {
        __syncthreads();
        {
            int row = tid >> 2; int col = (tid & 3) << 4;
            int m = mt*64 + row;
            float4* d4 = (float4*)&sS[row*68 + col];
            if (m < MM) {
                const float4* s4 = (const float4*)(sb + (size_t)m*64 + col);
                d4[0]=s4[0]; d4[1]=s4[1]; d4[2]=s4[2]; d4[3]=s4[3];
            } else {
                float4 z = {0,0,0,0};
                d4[0]=z; d4[1]=z; d4[2]=z; d4[3]=z;
            }
        }
        __syncthreads();
        bool tail = (mt == 34);
        #pragma unroll
        for (int nt=0; nt<4; nt++) {
            float C0[4] = {0,0,0,0};
            float C1[4] = {0,0,0,0};
            const float* pB = &sS[(n0 + nt*8 + g)*68 + q4];
            #pragma unroll
            for (int kc=0;kc<8;kc++) {
                unsigned bb0 = __float_as_uint(pB[kc*8]);
                unsigned bb1 = __float_as_uint(pB[kc*8 + 4]);
                MMA_TF32(C0, afr[0][kc], bb0, bb1);
                MMA_TF32(C1, afr[1][kc], bb0, bb1);
            }
            if (tail) {
                int col0 = mt*64 + n0 + nt*8 + (q4<<1);
                if (col0 < MM) {
                    ins3(C0[0], top[0][0][0], top[0][0][1], top[0][0][2]);
                    ins3(C0[2], top[0][1][0], top[0][1][1], top[0][1][2]);
                    ins3(C1[0], top[1][0][0], top[1][0][1], top[1][0][2]);
                    ins3(C1[2], top[1][1][0], top[1][1][1], top[1][1][2]);
                }
                if (col0+1 < MM) {
                    ins3(C0[1], top[0][0][0], top[0][0][1], top[0][0][2]);
                    ins3(C0[3], top[0][1][0], top[0][1][1], top[0][1][2]);
                    ins3(C1[1], top[1][0][0], top[1][0][1], top[1][0][2]);
                    ins3(C1[3], top[1][1][0], top[1][1][1], top[1][1][2]);
                }
            } else {
                ins3(C0[0], top[0][0][0], top[0][0][1], top[0][0][2]);
                ins3(C0[1], top[0][0][0], top[0][0][1], top[0][0][2]);
                ins3(C0[2], top[0][1][0], top[0][1][1], top[0][1][2]);
                ins3(C0[3], top[0][1][0], top[0][1][1], top[0][1][2]);
                ins3(C1[0], top[1][0][0], top[1][0][1], top[1][0][2]);
                ins3(C1[1], top[1][0][0], top[1][0][1], top[1][0][2]);
                ins3(C1[2], top[1][1][0], top[1][1][1], top[1][1][2]);
                ins3(C1[3], top[1][1][0], top[1][1][1], top[1][1][2]);
            }
        }
    }
    // merge across the 4 lanes (q4) sharing each row
    #pragma unroll
    for (int ofs=1; ofs<=2; ofs<<=1) {
        #pragma unroll
        for (int qq=0;qq<2;qq++)
          #pragma unroll
          for (int h=0;h<2;h++) {
            float o0 = __shfl_xor_sync(0xffffffffu, top[qq][h][0], ofs);
            float o1 = __shfl_xor_sync(0xffffffffu, top[qq][h][1], ofs);
            float o2 = __shfl_xor_sync(0xffffffffu, top[qq][h][2], ofs);
            ins3(o0, top[qq][h][0], top[qq][h][1], top[qq][h][2]);
            ins3(o1, top[qq][h][0], top[qq][h][1], top[qq][h][2]);
            ins3(o2, top[qq][h][0], top[qq][h][1], top[qq][h][2]);
          }
    }
    if (q4 == 0) {
        #pragma unroll
        for (int qq=0;qq<2;qq++) {
            int rA = r0 + g;
            #pragma unroll
            for (int k=0;k<3;k++) {
                smg[((qq*64 + rA    )*2 + cg)*3 + k] = top[qq][0][k];
                smg[((qq*64 + rA + 8)*2 + cg)*3 + k] = top[qq][1][k];
            }
        }
    }
    __syncthreads();
    if (tid < 128) {
        int qq = tid >> 6, row = tid & 63;
        float m0 = smg[((qq*64+row)*2+0)*3+0];
        float m1 = smg[((qq*64+row)*2+0)*3+1];
        float m2 = smg[((qq*64+row)*2+0)*3+2];
        ins3(smg[((qq*64+row)*2+1)*3+0], m0,m1,m2);
        ins3(smg[((qq*64+row)*2+1)*3+1], m0,m1,m2);
        ins3(smg[((qq*64+row)*2+1)*3+2], m0,m1,m2);
        if (lt*64 + row < LL) atomicAdd(&bs[qq], m0+m1+m2);
    }
    __syncthreads();
    if (tid < 2) atomicAdd(&out[(b*16 + qp*2 + tid)*5 + c], bs[tid]);
}

// ---------------- launcher ----------------
extern "C" void kernel_launch(void* const* d_in, const int* in_sizes, int n_in,
                              void* d_out, int out_size) {
    const float* query   = (const float*)d_in[0];
    const float* support = (const float*)d_in[1];
    const float* W1 = (const float*)d_in[2];
    const float* g1 = (const float*)d_in[3];
    const float* b1 = (const float*)d_in[4];
    const float* W2 = (const float*)d_in[5];
    const float* g2 = (const float*)d_in[6];
    const float* b2 = (const float*)d_in[7];
    const float* W3 = (const float*)d_in[8];
    const float* g3 = (const float*)d_in[9];
    const float* b3 = (const float*)d_in[10];
    const float* W4 = (const float*)d_in[11];
    const float* g4 = (const float*)d_in[12];
    const float* b4 = (const float*)d_in[13];
    float* out = (float*)d_out;

    cudaFuncSetAttribute(conv2_tc, cudaFuncAttributeMaxDynamicSharedMemorySize, 60192);
    cudaFuncSetAttribute(conv34_tc, cudaFuncAttributeMaxDynamicSharedMemorySize, 71232);
    cudaFuncSetAttribute(sim_kernel, cudaFuncAttributeMaxDynamicSharedMemorySize, 55304);

    prep_kernel<<<224, 256>>>(out, W1, W2, W3, W4);

    // block 1: conv1 -> g_A -> stats L0 -> pool -> g_Bf
    conv1_kernel<<<dim3(36,2,NIMG), 256>>>(query, support);
    bn_part_kernel<<<dim3(128,8), 256>>>(0, H1*H1, 0);
    {
        long long tot = (long long)NIMG*CH*H2*H2;
        bn_pool_kernel<<<(unsigned)((tot+255)/256), 256>>>(0, H1, g1, b1, 0);
    }
    // block 2: g_Bf -> g_Cf (TC) -> stats L1 -> pool -> g_A
    conv2_tc<<<dim3(9,NIMG), 256, 60192>>>();
    bn_part_kernel<<<dim3(128,8), 256>>>(2, H2*H2, 1);
    {
        long long tot = (long long)NIMG*CH*H3*H3;
        bn_pool_kernel<<<(unsigned)((tot+255)/256), 256>>>(1, H2, g2, b2, 1);
    }
    // block 3: g_A -> g_Cf (TC raw) -> stats L2
    conv34_tc<<<dim3(4,NIMG), 256, 71232>>>(0, g3, b3);
    bn_part_kernel<<<dim3(128,8), 256>>>(2, LL, 2);
    // block 4: g_Cf (BN L2 on read) -> g_Bf (TC) -> stats L3 -> normalize
    conv34_tc<<<dim3(4,NIMG), 256, 71232>>>(1, g3, b3);
    bn_part_kernel<<<dim3(128,8), 256>>>(1, LL, 3);
    normalize_kernel<<<dim3(2,NIMG), 256>>>(g4, b4);

    // cosine sim (tf32 tensor cores, 2 queries per block) + top-3 + sum
    sim_kernel<<<dim3(7,80), 256, 55304>>>(out);
}

// round 12
// speedup vs baseline: 4.3513x; 1.0837x over previous
#include <cuda_runtime.h>
#include <cuda_bf16.h>
#include <cstdint>

#define LRELU_SLOPE 0.2f
#define BN_EPS 1e-5f

#define NIMG 82
#define NQIMG 32
#define CH 64
#define H1 84
#define H2 42
#define H3 21
#define LL 441
#define MM 2205

// ---------------- scratch (device globals; no allocs allowed) ----------------
__device__ float g_A[(size_t)NIMG*CH*H1*H1];
__device__ float g_Bf[(size_t)NIMG*CH*H2*H2];
__device__ float g_Cf[(size_t)NIMG*CH*H2*H2];
__device__ float g_qn[(size_t)NQIMG*LL*CH];
__device__ float g_sn[(size_t)2*5*MM*CH];
__device__ float g_bnsum4[4*128*2];            // [layer][grp*64+c][{s,s2}]
__device__ float g_WT[64*9*64];                // conv1 weights [ci*9+k][co]
// bf16-split weight fragments: [cc(4)][s(9)][nt(8)][lane(32)][reg(2)]
__device__ uint32_t g_W2h[18432];
__device__ uint32_t g_W2l[18432];
__device__ uint32_t g_W3h[18432];
__device__ uint32_t g_W3l[18432];
__device__ uint32_t g_W4h[18432];
__device__ uint32_t g_W4l[18432];

__device__ __forceinline__ float lrelu(float x){ return x >= 0.f ? x : LRELU_SLOPE*x; }

__device__ __forceinline__ void ins3(float v, float& t0, float& t1, float& t2){
    if (v > t2) {
        float s  = fminf(t0, v);
        t0 = fmaxf(t0, v);
        float s2 = fminf(t1, s);
        t1 = fmaxf(t1, s);
        t2 = fmaxf(t2, s2);
    }
}

// split fp32 pair into bf16x2 hi + bf16x2 lo (v = hi + lo, error ~2^-18)
__device__ __forceinline__ void split2(float vx, float vy, uint32_t& hi, uint32_t& lo){
    __nv_bfloat162 h = __floats2bfloat162_rn(vx, vy);
    float hx = __bfloat162float(h.x);
    float hy = __bfloat162float(h.y);
    __nv_bfloat162 l = __floats2bfloat162_rn(vx - hx, vy - hy);
    hi = *reinterpret_cast<uint32_t*>(&h);
    lo = *reinterpret_cast<uint32_t*>(&l);
}

#define MMA_BF16(C, A, b0, b1) \
    asm volatile("mma.sync.aligned.m16n8k16.row.col.f32.bf16.bf16.f32 " \
        "{%0,%1,%2,%3},{%4,%5,%6,%7},{%8,%9},{%0,%1,%2,%3};" \
        : "+f"((C)[0]), "+f"((C)[1]), "+f"((C)[2]), "+f"((C)[3]) \
        : "r"((A)[0]), "r"((A)[1]), "r"((A)[2]), "r"((A)[3]), "r"(b0), "r"(b1))

#define MMA_TF32(C, A, b0, b1) \
    asm volatile("mma.sync.aligned.m16n8k8.row.col.f32.tf32.tf32.f32 " \
        "{%0,%1,%2,%3},{%4,%5,%6,%7},{%8,%9},{%0,%1,%2,%3};" \
        : "+f"((C)[0]), "+f"((C)[1]), "+f"((C)[2]), "+f"((C)[3]) \
        : "r"((A)[0]), "r"((A)[1]), "r"((A)[2]), "r"((A)[3]), "r"(b0), "r"(b1))

// BN scale/shift from per-layer raw sums
__device__ __forceinline__ void bn_sc(int layer, int gc, float HW, float gamma, float beta,
                                      float& sc, float& sh){
    float s  = g_bnsum4[(layer*128 + gc)*2 + 0];
    float s2 = g_bnsum4[(layer*128 + gc)*2 + 1];
    float cnt = ((gc >= 64) ? 50.f : 32.f) * HW;
    float mean = s / cnt;
    float var = s2 / cnt - mean*mean;
    float inv = rsqrtf(var + BN_EPS);
    sc = gamma * inv;
    sh = beta - mean * sc;
}

// ---------------- prep: zero + conv1 wtrans + conv2/3/4 frag pack ------------
__device__ __forceinline__ void frag_compute(const float* __restrict__ W, int i,
                                             uint32_t& hi, uint32_t& lo){
    int r  = i & 1;
    int t  = (i >> 1) & 31;
    int nt = (i >> 6) & 7;
    int rem = i >> 9;
    int s  = rem % 9;
    int cc = rem / 9;
    int q = t & 3, nn = t >> 2;
    int ci = cc*16 + 2*q + 8*r;
    int co = nt*8 + nn;
    float v0 = W[((size_t)co*64 + ci    )*9 + s];
    float v1 = W[((size_t)co*64 + ci + 1)*9 + s];
    split2(v0, v1, hi, lo);
}

__global__ void prep_kernel(float* out, const float* __restrict__ W1,
                            const float* __restrict__ W2, const float* __restrict__ W3,
                            const float* __restrict__ W4){
    int bx = blockIdx.x, tid = threadIdx.x;
    if (bx == 0) {
        if (tid < 160) out[tid] = 0.f;
        for (int i = tid; i < 4*128*2; i += 256) g_bnsum4[i] = 0.f;
    } else if (bx < 8) {
        int i = (bx-1)*256 + tid;
        if (i < 3*9*64) {
            int co = i & 63, r = i >> 6;
            int ci = r / 9, k = r % 9;
            g_WT[i] = W1[(size_t)co*3*9 + ci*9 + k];
        }
    } else if (bx < 80) {
        int i = (bx-8)*256 + tid;
        uint32_t hi, lo; frag_compute(W2, i, hi, lo);
        g_W2h[i] = hi; g_W2l[i] = lo;
    } else if (bx < 152) {
        int i = (bx-80)*256 + tid;
        uint32_t hi, lo; frag_compute(W3, i, hi, lo);
        g_W3h[i] = hi; g_W3l[i] = lo;
    } else {
        int i = (bx-152)*256 + tid;
        uint32_t hi, lo; frag_compute(W4, i, hi, lo);
        g_W4h[i] = hi; g_W4l[i] = lo;
    }
}

// ---------------- conv1: 3->64 @ 84x84, pad 1 (writes g_A) ----------------
__global__ void __launch_bounds__(256,3) conv1_kernel(const float* __restrict__ query,
                                                      const float* __restrict__ support) {
    __shared__ float swt[27*32];
    __shared__ float sin[3*18*18];
    int n = blockIdx.z, coH = blockIdx.y;
    int bx = blockIdx.x;
    int x0 = (bx % 6) * 16, y0 = (bx / 6) * 16;
    int tid = threadIdx.x;
    int tx = tid & 15, ty = tid >> 4;
    for (int i = tid; i < 864; i += 256) {
        int kk = i >> 5, co = i & 31;
        swt[i] = g_WT[kk*64 + coH*32 + co];
    }
    const float* img = (n < NQIMG) ? (query + (size_t)n*3*H1*H1)
                                   : (support + (size_t)(n-NQIMG)*3*H1*H1);
    for (int i = tid; i < 972; i += 256) {
        int ci = i / 324, rem = i % 324;
        int yy = rem / 18, xx = rem % 18;
        int gy = y0 - 1 + yy, gx = x0 - 1 + xx;
        sin[i] = (gy>=0 && gy<H1 && gx>=0 && gx<H1) ? img[(size_t)ci*H1*H1 + gy*H1 + gx] : 0.f;
    }
    __syncthreads();
    float r[27];
    #pragma unroll
    for (int ci=0;ci<3;ci++)
      #pragma unroll
      for (int dy=0;dy<3;dy++)
        #pragma unroll
        for (int dx=0;dx<3;dx++)
          r[ci*9+dy*3+dx] = sin[ci*324 + (ty+dy)*18 + (tx+dx)];
    float acc[32];
    #pragma unroll
    for (int i=0;i<32;i++) acc[i]=0.f;
    const float4* swt4 = (const float4*)swt;
    #pragma unroll
    for (int kk=0; kk<27; kk++) {
        float v = r[kk];
        #pragma unroll
        for (int c4=0; c4<8; c4++) {
            float4 w = swt4[kk*8 + c4];
            acc[c4*4+0] += w.x*v;
            acc[c4*4+1] += w.y*v;
            acc[c4*4+2] += w.z*v;
            acc[c4*4+3] += w.w*v;
        }
    }
    int y = y0+ty, x = x0+tx;
    if (y < H1 && x < H1) {
        size_t obase = ((size_t)n*CH + coH*32)*H1*H1 + (size_t)y*H1 + x;
        #pragma unroll 4
        for (int co=0; co<32; co++) g_A[obase + (size_t)co*H1*H1] = acc[co];
    }
}

// ---------------- BN partial stats -> g_bnsum4[layer] ----------------
__global__ void bn_part_kernel(int srcSel, int HW, int layer){
    const float* src = (srcSel==0) ? g_A : (srcSel==1) ? g_Bf : g_Cf;
    int gc = blockIdx.x;
    int grp = gc >> 6, c = gc & 63;
    int slice = blockIdx.y;
    int n0, n1;
    if (!grp) { n0 = slice*4; n1 = n0+4; }
    else { n0 = 32 + (50*slice)/8; n1 = 32 + (50*(slice+1))/8; }
    float s = 0.f, s2 = 0.f;
    if ((HW & 3) == 0) {
        int m = HW >> 2;
        for (int n=n0; n<n1; n++) {
            const float4* p = (const float4*)(src + ((size_t)n*CH + c)*HW);
            for (int i=threadIdx.x; i<m; i+=256) {
                float4 v = p[i];
                s  += v.x + v.y + v.z + v.w;
                s2 += v.x*v.x + v.y*v.y + v.z*v.z + v.w*v.w;
            }
        }
    } else {
        for (int n=n0; n<n1; n++) {
            const float* p = src + ((size_t)n*CH + c)*HW;
            for (int i=threadIdx.x; i<HW; i+=256) {
                float v = p[i]; s += v; s2 += v*v;
            }
        }
    }
    __shared__ float sh1[256], sh2[256];
    sh1[threadIdx.x]=s; sh2[threadIdx.x]=s2;
    __syncthreads();
    for (int ofs=128; ofs>0; ofs>>=1) {
        if (threadIdx.x<ofs){ sh1[threadIdx.x]+=sh1[threadIdx.x+ofs]; sh2[threadIdx.x]+=sh2[threadIdx.x+ofs]; }
        __syncthreads();
    }
    if (threadIdx.x==0) {
        atomicAdd(&g_bnsum4[(layer*128+gc)*2+0], sh1[0]);
        atomicAdd(&g_bnsum4[(layer*128+gc)*2+1], sh2[0]);
    }
}

// ---------------- BN + LReLU + 2x2 maxpool (templated, per-(n,c) block) ------
// DIR 0: g_A -> g_Bf (HI=84, layer 0); DIR 1: g_Cf -> g_A (HI=42, layer 1)
template<int HI, int DIR, int LAYER>
__global__ void bn_pool_t(const float* __restrict__ gamma, const float* __restrict__ beta) {
    constexpr int HO = HI/2;
    int nc = blockIdx.y;
    int n = nc >> 6, c = nc & 63;
    int grp = (n < NQIMG) ? 0 : 1;
    float sc, sh;
    bn_sc(LAYER, grp*64+c, (float)(HI*HI), gamma[c], beta[c], sc, sh);
    const float* base = (DIR ? g_Cf : g_A) + (size_t)nc*HI*HI;
    float* obase = (DIR ? g_A : g_Bf) + (size_t)nc*HO*HO;
    int idx = blockIdx.x*256 + threadIdx.x;
    if (idx >= HO*HO) return;
    int y = idx / HO, x = idx % HO;
    const float* p = base + (2*y)*HI + 2*x;
    float2 r0 = *(const float2*)p;
    float2 r1 = *(const float2*)(p + HI);
    float a = lrelu(r0.x*sc+sh);
    float b = lrelu(r0.y*sc+sh);
    float c2 = lrelu(r1.x*sc+sh);
    float d = lrelu(r1.y*sc+sh);
    obase[idx] = fmaxf(fmaxf(a,b), fmaxf(c2,d));
}

// ---------------- conv2 (bf16 pre-split tensor core implicit GEMM) -----------
// smem: sInH/sInL [324 pos][9 pad] uint32 (bf16x2 of ci pair), weights after.
__global__ void __launch_bounds__(256,3) conv2_tc() {
    extern __shared__ uint32_t smu[];
    uint32_t* sInH = smu;                 // 2916 (mult of 4 -> 16B aligned banks)
    uint32_t* sInL = sInH + 2916;         // 2916
    uint32_t* sWh  = sInL + 2916;         // 4608 (byte off 23328, %16==0)
    uint32_t* sWl  = sWh + 4608;          // 4608  -> total 15048 u32 = 60192 B
    int n = blockIdx.y;
    int bx = blockIdx.x;
    int x0 = (bx % 3) * 16, y0 = (bx / 3) * 16;
    int tid = threadIdx.x;
    int w = tid >> 5, lane = tid & 31, g = lane >> 2, q4 = lane & 3;
    float acc[2][8][4];
    #pragma unroll
    for (int i=0;i<2;i++)
      #pragma unroll
      for (int nt=0;nt<8;nt++)
        #pragma unroll
        for (int r=0;r<4;r++) acc[i][nt][r]=0.f;
    const float* ibase = g_Bf + (size_t)n*CH*H2*H2;
    for (int cc=0; cc<4; cc++) {
        __syncthreads();
        // stage: read pairs of ci planes, split once, store bf16x2 hi/lo
        for (int i=tid; i<2592; i+=256) {
            int cp = i / 324, pos = i % 324;
            int yy = pos / 18, xx = pos % 18;
            int gy = y0 - 1 + yy, gx = x0 - 1 + xx;
            float v0 = 0.f, v1 = 0.f;
            if (gy>=0 && gy<H2 && gx>=0 && gx<H2) {
                const float* pp = ibase + (size_t)(cc*16 + 2*cp)*H2*H2 + gy*H2 + gx;
                v0 = pp[0];
                v1 = pp[H2*H2];
            }
            uint32_t hi, lo;
            split2(v0, v1, hi, lo);
            sInH[pos*9 + cp] = hi;
            sInL[pos*9 + cp] = lo;
        }
        {
            const uint4* sh = (const uint4*)(g_W2h + cc*4608);
            const uint4* sl = (const uint4*)(g_W2l + cc*4608);
            uint4* dh = (uint4*)sWh;
            uint4* dl = (uint4*)sWl;
            for (int i=tid; i<1152; i+=256) { dh[i]=sh[i]; dl[i]=sl[i]; }
        }
        __syncthreads();
        for (int s=0; s<9; s++) {
            int dy = s / 3, dx = s - 3*dy;
            uint32_t Ah[2][4], Al[2][4];
            #pragma unroll
            for (int i=0;i<2;i++) {
                int yy = 2*w + i + dy;
                const uint32_t* pH0 = &sInH[(yy*18 + g + dx)*9];
                const uint32_t* pH1 = &sInH[(yy*18 + g + 8 + dx)*9];
                const uint32_t* pL0 = &sInL[(yy*18 + g + dx)*9];
                const uint32_t* pL1 = &sInL[(yy*18 + g + 8 + dx)*9];
                Ah[i][0] = pH0[q4];   Ah[i][1] = pH1[q4];
                Ah[i][2] = pH0[q4+4]; Ah[i][3] = pH1[q4+4];
                Al[i][0] = pL0[q4];   Al[i][1] = pL1[q4];
                Al[i][2] = pL0[q4+4]; Al[i][3] = pL1[q4+4];
            }
            #pragma unroll
            for (int nt=0; nt<8; nt++) {
                int wb = s*512 + nt*64 + lane*2;
                uint32_t bh0 = sWh[wb], bh1 = sWh[wb+1];
                uint32_t bl0 = sWl[wb], bl1 = sWl[wb+1];
                #pragma unroll
                for (int i=0;i<2;i++) {
                    MMA_BF16(acc[i][nt], Ah[i], bh0, bh1);
                    MMA_BF16(acc[i][nt], Ah[i], bl0, bl1);
                    MMA_BF16(acc[i][nt], Al[i], bh0, bh1);
                }
            }
        }
    }
    #pragma unroll
    for (int i=0;i<2;i++) {
        int y = y0 + 2*w + i;
        if (y >= H2) continue;
        int xA = x0 + g, xB = x0 + g + 8;
        bool vB = (xB < H2);
        #pragma unroll
        for (int nt=0; nt<8; nt++) {
            int co = nt*8 + 2*q4;
            size_t p0 = ((size_t)(n*CH + co    )*H2 + y)*H2;
            size_t p1 = ((size_t)(n*CH + co + 1)*H2 + y)*H2;
            g_Cf[p0 + xA] = acc[i][nt][0];
            g_Cf[p1 + xA] = acc[i][nt][1];
            if (vB) {
                g_Cf[p0 + xB] = acc[i][nt][2];
                g_Cf[p1 + xB] = acc[i][nt][3];
            }
        }
    }
}

// ---------------- conv3/conv4 (bf16 pre-split TC) @ 21x21, 1 tile/warp -------
// which 0: g_A -> g_Cf (W3); which 1: g_Cf -> g_Bf (BN L2 on read, W4)
// sIn banks padded to 4764 u32 (multiple of 4) so sWh/sWl stay 16B-aligned.
__global__ void __launch_bounds__(256,3) conv34_tc(int which, const float* __restrict__ gamma,
                                                   const float* __restrict__ beta) {
    extern __shared__ uint32_t smu[];
    uint32_t* sInH = smu;                 // 4764 (529*9=4761 used, +3 pad)
    uint32_t* sInL = sInH + 4764;         // 4764
    uint32_t* sWh  = sInL + 4764;         // byte off 38112, %16==0
    uint32_t* sWl  = sWh + 4608;
    float* sc3 = (float*)(sWl + 4608);    // 64
    float* sh3 = sc3 + 64;                // 64  -> total 75488 B
    const float* src = which ? g_Cf : g_A;
    float* dst = which ? g_Bf : g_Cf;
    int n = blockIdx.y;
    int quarter = blockIdx.x;
    int grp = (n < NQIMG) ? 0 : 1;
    int tid = threadIdx.x;
    int w = tid >> 5, lane = tid & 31, g = lane >> 2, q4 = lane & 3;
    if (which && tid < 64) {
        float a, b;
        bn_sc(2, grp*64+tid, (float)LL, gamma[tid], beta[tid], a, b);
        sc3[tid] = a; sh3[tid] = b;
    }
    int t = quarter*7 + w;
    bool wact = (w < 7);
    int p0 = t*16 + g, p1 = p0 + 8;
    bool pv0 = wact && (p0 < LL), pv1 = wact && (p1 < LL);
    int py0 = p0/21, px0 = p0%21, py1 = p1/21, px1 = p1%21;
    float acc[8][4];
    #pragma unroll
    for (int nt=0;nt<8;nt++)
      #pragma unroll
      for (int r=0;r<4;r++) acc[nt][r]=0.f;
    const float* ibase = src + (size_t)n*CH*LL;
    const uint32_t* Wh = which ? g_W4h : g_W3h;
    const uint32_t* Wl = which ? g_W4l : g_W3l;
    for (int cc=0; cc<4; cc++) {
        __syncthreads();
        for (int i=tid; i<4232; i+=256) {
            int cp = i / 529, pos = i % 529;
            int yy = pos / 23, xx = pos % 23;
            int gy = yy - 1, gx = xx - 1;
            float v0 = 0.f, v1 = 0.f;
            if (gy>=0 && gy<H3 && gx>=0 && gx<H3) {
                const float* pp = ibase + (size_t)(cc*16 + 2*cp)*LL + gy*21 + gx;
                v0 = pp[0];
                v1 = pp[LL];
                if (which) {
                    int c0i = cc*16 + 2*cp;
                    v0 = lrelu(v0*sc3[c0i] + sh3[c0i]);
                    v1 = lrelu(v1*sc3[c0i+1] + sh3[c0i+1]);
                }
            }
            uint32_t hi, lo;
            split2(v0, v1, hi, lo);
            sInH[pos*9 + cp] = hi;
            sInL[pos*9 + cp] = lo;
        }
        {
            const uint4* sh = (const uint4*)(Wh + cc*4608);
            const uint4* sl = (const uint4*)(Wl + cc*4608);
            uint4* dh = (uint4*)sWh;
            uint4* dl = (uint4*)sWl;
            for (int i=tid; i<1152; i+=256) { dh[i]=sh[i]; dl[i]=sl[i]; }
        }
        __syncthreads();
        if (wact) {
            for (int s=0; s<9; s++) {
                int dy = s / 3, dx = s - 3*dy;
                uint32_t Ah[4] = {0,0,0,0}, Al[4] = {0,0,0,0};
                if (pv0) {
                    const uint32_t* pH = &sInH[((py0+dy)*23 + px0+dx)*9];
                    const uint32_t* pL = &sInL[((py0+dy)*23 + px0+dx)*9];
                    Ah[0] = pH[q4]; Ah[2] = pH[q4+4];
                    Al[0] = pL[q4]; Al[2] = pL[q4+4];
                }
                if (pv1) {
                    const uint32_t* pH = &sInH[((py1+dy)*23 + px1+dx)*9];
                    const uint32_t* pL = &sInL[((py1+dy)*23 + px1+dx)*9];
                    Ah[1] = pH[q4]; Ah[3] = pH[q4+4];
                    Al[1] = pL[q4]; Al[3] = pL[q4+4];
                }
                #pragma unroll
                for (int nt=0; nt<8; nt++) {
                    int wb = s*512 + nt*64 + lane*2;
                    uint32_t bh0 = sWh[wb], bh1 = sWh[wb+1];
                    uint32_t bl0 = sWl[wb], bl1 = sWl[wb+1];
                    MMA_BF16(acc[nt], Ah, bh0, bh1);
                    MMA_BF16(acc[nt], Ah, bl0, bl1);
                    MMA_BF16(acc[nt], Al, bh0, bh1);
                }
            }
        }
    }
    #pragma unroll
    for (int nt=0; nt<8; nt++) {
        int co = nt*8 + 2*q4;
        size_t b0 = ((size_t)n*CH + co    )*LL;
        size_t b1 = ((size_t)n*CH + co + 1)*LL;
        if (pv0) {
            dst[b0 + p0] = acc[nt][0];
            dst[b1 + p0] = acc[nt][1];
        }
        if (pv1) {
            dst[b0 + p1] = acc[nt][2];
            dst[b1 + p1] = acc[nt][3];
        }
    }
}

// ---------------- BN4 + LReLU + L2-normalize + tf32-round + transpose --------
__global__ void normalize_kernel(const float* __restrict__ gamma, const float* __restrict__ beta) {
    __shared__ float sc4[64], sh4[64];
    int n = blockIdx.y;
    int grp = (n < NQIMG) ? 0 : 1;
    if (threadIdx.x < 64) {
        float a, b;
        bn_sc(3, grp*64+threadIdx.x, (float)LL, gamma[threadIdx.x], beta[threadIdx.x], a, b);
        sc4[threadIdx.x] = a; sh4[threadIdx.x] = b;
    }
    __syncthreads();
    int l = blockIdx.x*256 + threadIdx.x;
    if (l >= LL) return;
    float v[64];
    float ss = 0.f;
    const float* p = g_Bf + (size_t)n*CH*LL + l;
    #pragma unroll
    for (int c=0;c<64;c++) {
        float t = lrelu(p[(size_t)c*LL]*sc4[c] + sh4[c]);
        v[c] = t; ss += t*t;
    }
    float inv = 1.f / fmaxf(sqrtf(ss), 1e-12f);
    float* dstp;
    if (n < NQIMG) {
        dstp = &g_qn[((size_t)n*LL + l)*64];
    } else {
        int ns = n - NQIMG;
        int b = ns/25, w = (ns%25)/5, s = ns%5;
        dstp = &g_sn[(((size_t)(b*5+w))*MM + (size_t)s*LL + l)*64];
    }
    #pragma unroll
    for (int c=0;c<64;c++) {
        float o = v[c]*inv;
        uint32_t ot;
        asm("cvt.rna.tf32.f32 %0, %1;" : "=r"(ot) : "f"(o));
        dstp[c] = __uint_as_float(ot);
    }
}

// ---------------- similarity: tf32 mma, 2 queries/block ----------------
__global__ void __launch_bounds__(256,2) sim_kernel(float* __restrict__ out) {
    extern __shared__ float smem[];
    float* sQ  = smem;            // 2*64*68 = 8704
    float* sS  = sQ + 8704;       // 64*68 = 4352
    float* smg = sS + 4352;       // 2*64*2*3 = 768
    float* bs  = smg + 768;       // 2
    int lt = blockIdx.x;
    int bc = blockIdx.y;
    int b = bc/40; int qp = (bc/5)%8; int c = bc%5;
    const float* sb = g_sn + ((size_t)(b*5+c))*MM*64;
    int tid = threadIdx.x;
    int w = tid >> 5, lane = tid & 31;
    int g = lane >> 2, q4 = lane & 3;
    int rg = w & 3, cg = w >> 2;
    #pragma unroll
    for (int qq=0; qq<2; qq++) {
        const float* qb = g_qn + ((size_t)(b*16 + qp*2 + qq))*LL*64;
        int row = tid >> 2; int col = (tid & 3) << 4;
        int grow = lt*64 + row;
        float4* d4 = (float4*)&sQ[qq*4352 + row*68 + col];
        if (grow < LL) {
            const float4* s4 = (const float4*)(qb + (size_t)grow*64 + col);
            d4[0]=s4[0]; d4[1]=s4[1]; d4[2]=s4[2]; d4[3]=s4[3];
        } else {
            float4 z = {0,0,0,0};
            d4[0]=z; d4[1]=z; d4[2]=z; d4[3]=z;
        }
    }
    if (tid < 2) bs[tid] = 0.f;
    __syncthreads();
    int r0 = rg*16;
    unsigned afr[2][8][4];
    #pragma unroll
    for (int qq=0; qq<2; qq++) {
        const float* qa = &sQ[qq*4352 + (r0+g)*68 + q4];
        #pragma unroll
        for (int kc=0;kc<8;kc++) {
            afr[qq][kc][0] = __float_as_uint(qa[kc*8]);
            afr[qq][kc][1] = __float_as_uint(qa[8*68 + kc*8]);
            afr[qq][kc][2] = __float_as_uint(qa[kc*8 + 4]);
            afr[qq][kc][3] = __float_as_uint(qa[8*68 + kc*8 + 4]);
        }
    }
    float top[2][2][3];
    #pragma unroll
    for (int qq=0;qq<2;qq++)
      #pragma unroll
      for (int h=0;h<2;h++)
        #pragma unroll
        for (int k=0;k<3;k++) top[qq][h][k] = -1e30f;
    int n0 = cg*32;
    for (int mt=0; mt<35; mt++) {
        __syncthreads();
        {
            int row = tid >> 2; int col = (tid & 3) << 4;
            int m = mt*64 + row;
            float4* d4 = (float4*)&sS[row*68 + col];
            if (m < MM) {
                const float4* s4 = (const float4*)(sb + (size_t)m*64 + col);
                d4[0]=s4[0]; d4[1]=s4[1]; d4[2]=s4[2]; d4[3]=s4[3];
            } else {
                float4 z = {0,0,0,0};
                d4[0]=z; d4[1]=z; d4[2]=z; d4[3]=z;
            }
        }
        __syncthreads();
        bool tail = (mt == 34);
        #pragma unroll
        for (int nt=0; nt<4; nt++) {
            float C0[4] = {0,0,0,0};
            float C1[4] = {0,0,0,0};
            const float* pB = &sS[(n0 + nt*8 + g)*68 + q4];
            #pragma unroll
            for (int kc=0;kc<8;kc++) {
                unsigned bb0 = __float_as_uint(pB[kc*8]);
                unsigned bb1 = __float_as_uint(pB[kc*8 + 4]);
                MMA_TF32(C0, afr[0][kc], bb0, bb1);
                MMA_TF32(C1, afr[1][kc], bb0, bb1);
            }
            if (tail) {
                int col0 = mt*64 + n0 + nt*8 + (q4<<1);
                if (col0 < MM) {
                    ins3(C0[0], top[0][0][0], top[0][0][1], top[0][0][2]);
                    ins3(C0[2], top[0][1][0], top[0][1][1], top[0][1][2]);
                    ins3(C1[0], top[1][0][0], top[1][0][1], top[1][0][2]);
                    ins3(C1[2], top[1][1][0], top[1][1][1], top[1][1][2]);
                }
                if (col0+1 < MM) {
                    ins3(C0[1], top[0][0][0], top[0][0][1], top[0][0][2]);
                    ins3(C0[3], top[0][1][0], top[0][1][1], top[0][1][2]);
                    ins3(C1[1], top[1][0][0], top[1][0][1], top[1][0][2]);
                    ins3(C1[3], top[1][1][0], top[1][1][1], top[1][1][2]);
                }
            } else {
                ins3(C0[0], top[0][0][0], top[0][0][1], top[0][0][2]);
                ins3(C0[1], top[0][0][0], top[0][0][1], top[0][0][2]);
                ins3(C0[2], top[0][1][0], top[0][1][1], top[0][1][2]);
                ins3(C0[3], top[0][1][0], top[0][1][1], top[0][1][2]);
                ins3(C1[0], top[1][0][0], top[1][0][1], top[1][0][2]);
                ins3(C1[1], top[1][0][0], top[1][0][1], top[1][0][2]);
                ins3(C1[2], top[1][1][0], top[1][1][1], top[1][1][2]);
                ins3(C1[3], top[1][1][0], top[1][1][1], top[1][1][2]);
            }
        }
    }
    #pragma unroll
    for (int ofs=1; ofs<=2; ofs<<=1) {
        #pragma unroll
        for (int qq=0;qq<2;qq++)
          #pragma unroll
          for (int h=0;h<2;h++) {
            float o0 = __shfl_xor_sync(0xffffffffu, top[qq][h][0], ofs);
            float o1 = __shfl_xor_sync(0xffffffffu, top[qq][h][1], ofs);
            float o2 = __shfl_xor_sync(0xffffffffu, top[qq][h][2], ofs);
            ins3(o0, top[qq][h][0], top[qq][h][1], top[qq][h][2]);
            ins3(o1, top[qq][h][0], top[qq][h][1], top[qq][h][2]);
            ins3(o2, top[qq][h][0], top[qq][h][1], top[qq][h][2]);
          }
    }
    if (q4 == 0) {
        #pragma unroll
        for (int qq=0;qq<2;qq++) {
            int rA = r0 + g;
            #pragma unroll
            for (int k=0;k<3;k++) {
                smg[((qq*64 + rA    )*2 + cg)*3 + k] = top[qq][0][k];
                smg[((qq*64 + rA + 8)*2 + cg)*3 + k] = top[qq][1][k];
            }
        }
    }
    __syncthreads();
    if (tid < 128) {
        int qq = tid >> 6, row = tid & 63;
        float m0 = smg[((qq*64+row)*2+0)*3+0];
        float m1 = smg[((qq*64+row)*2+0)*3+1];
        float m2 = smg[((qq*64+row)*2+0)*3+2];
        ins3(smg[((qq*64+row)*2+1)*3+0], m0,m1,m2);
        ins3(smg[((qq*64+row)*2+1)*3+1], m0,m1,m2);
        ins3(smg[((qq*64+row)*2+1)*3+2], m0,m1,m2);
        if (lt*64 + row < LL) atomicAdd(&bs[qq], m0+m1+m2);
    }
    __syncthreads();
    if (tid < 2) atomicAdd(&out[(b*16 + qp*2 + tid)*5 + c], bs[tid]);
}

// ---------------- launcher ----------------
extern "C" void kernel_launch(void* const* d_in, const int* in_sizes, int n_in,
                              void* d_out, int out_size) {
    const float* query   = (const float*)d_in[0];
    const float* support = (const float*)d_in[1];
    const float* W1 = (const float*)d_in[2];
    const float* g1 = (const float*)d_in[3];
    const float* b1 = (const float*)d_in[4];
    const float* W2 = (const float*)d_in[5];
    const float* g2 = (const float*)d_in[6];
    const float* b2 = (const float*)d_in[7];
    const float* W3 = (const float*)d_in[8];
    const float* g3 = (const float*)d_in[9];
    const float* b3 = (const float*)d_in[10];
    const float* W4 = (const float*)d_in[11];
    const float* g4 = (const float*)d_in[12];
    const float* b4 = (const float*)d_in[13];
    float* out = (float*)d_out;

    cudaFuncSetAttribute(conv2_tc, cudaFuncAttributeMaxDynamicSharedMemorySize, 60192);
    cudaFuncSetAttribute(conv34_tc, cudaFuncAttributeMaxDynamicSharedMemorySize, 75488);
    cudaFuncSetAttribute(sim_kernel, cudaFuncAttributeMaxDynamicSharedMemorySize, 55304);

    prep_kernel<<<224, 256>>>(out, W1, W2, W3, W4);

    // block 1: conv1 -> g_A -> stats L0 -> pool -> g_Bf
    conv1_kernel<<<dim3(36,2,NIMG), 256>>>(query, support);
    bn_part_kernel<<<dim3(128,8), 256>>>(0, H1*H1, 0);
    bn_pool_t<84,0,0><<<dim3(7, NIMG*CH), 256>>>(g1, b1);
    // block 2: g_Bf -> g_Cf (TC) -> stats L1 -> pool -> g_A
    conv2_tc<<<dim3(9,NIMG), 256, 60192>>>();
    bn_part_kernel<<<dim3(128,8), 256>>>(2, H2*H2, 1);
    bn_pool_t<42,1,1><<<dim3(2, NIMG*CH), 256>>>(g2, b2);
    // block 3: g_A -> g_Cf (TC raw) -> stats L2
    conv34_tc<<<dim3(4,NIMG), 256, 75488>>>(0, g3, b3);
    bn_part_kernel<<<dim3(128,8), 256>>>(2, LL, 2);
    // block 4: g_Cf (BN L2 on read) -> g_Bf (TC) -> stats L3 -> normalize
    conv34_tc<<<dim3(4,NIMG), 256, 75488>>>(1, g3, b3);
    bn_part_kernel<<<dim3(128,8), 256>>>(1, LL, 3);
    normalize_kernel<<<dim3(2,NIMG), 256>>>(g4, b4);

    // cosine sim (tf32 tensor cores, 2 queries per block) + top-3 + sum
    sim_kernel<<<dim3(7,80), 256, 55304>>>(out);
}